// round 15
// baseline (speedup 1.0000x reference)
#include <cuda_runtime.h>
#include <cuda_bf16.h>
#include <math.h>
#include <stdint.h>

#define EMB 1024
#define SEQ 1024
#define BATCH 4
#define NH 16
#define HD 64

// ---------------- scratch (device globals; no allocation allowed) ----------
__device__ float g_q[BATCH * SEQ * EMB];
__device__ float g_k[BATCH * SEQ * EMB];
__device__ float g_v[BATCH * SEQ * EMB];
__device__ float g_ctx[BATCH * SEQ * EMB];
__device__ float g_cw[BATCH * SEQ * NH];
__device__ float g_vsuf[BATCH * NH * SEQ * HD];
__device__ __nv_bfloat16 g_ahi[3][BATCH * SEQ * EMB];
__device__ __nv_bfloat16 g_alo[3][BATCH * SEQ * EMB];
__device__ __nv_bfloat16 g_whi[4][EMB * EMB];
__device__ __nv_bfloat16 g_wlo[4][EMB * EMB];

// ---------------- fast exp: FFMA-only ---------------------------------------
__device__ __forceinline__ float fast_exp(float x)
{
    x = fmaxf(x, -80.0f);
    const float L2E = 1.4426950408889634f;
    float t = fmaf(x, L2E, 12582912.0f);
    float i = t - 12582912.0f;
    float f = fmaf(x, L2E, -i);
    float p = 1.3333558146e-3f;
    p = fmaf(p, f, 9.6181291918e-3f);
    p = fmaf(p, f, 5.5504108664e-2f);
    p = fmaf(p, f, 2.4022650696e-1f);
    p = fmaf(p, f, 6.9314718056e-1f);
    p = fmaf(p, f, 1.0f);
    return __int_as_float(__float_as_int(p) + ((int)i << 23));
}

// ---------------- mma / ldmatrix helpers -------------------------------------
__device__ __forceinline__ void ldsm4(uint32_t* r, const void* p)
{
    uint32_t a = (uint32_t)__cvta_generic_to_shared(p);
    asm volatile("ldmatrix.sync.aligned.m8n8.x4.shared.b16 {%0,%1,%2,%3},[%4];"
                 : "=r"(r[0]), "=r"(r[1]), "=r"(r[2]), "=r"(r[3]) : "r"(a));
}
__device__ __forceinline__ void ldsm4t(uint32_t* r, const void* p)
{
    uint32_t a = (uint32_t)__cvta_generic_to_shared(p);
    asm volatile("ldmatrix.sync.aligned.m8n8.x4.trans.shared.b16 {%0,%1,%2,%3},[%4];"
                 : "=r"(r[0]), "=r"(r[1]), "=r"(r[2]), "=r"(r[3]) : "r"(a));
}
__device__ __forceinline__ void mma_bf16(float* c, const uint32_t* a,
                                         uint32_t b0, uint32_t b1)
{
    asm("mma.sync.aligned.m16n8k16.row.col.f32.bf16.bf16.f32 "
        "{%0,%1,%2,%3},{%4,%5,%6,%7},{%8,%9},{%0,%1,%2,%3};"
        : "+f"(c[0]), "+f"(c[1]), "+f"(c[2]), "+f"(c[3])
        : "r"(a[0]), "r"(a[1]), "r"(a[2]), "r"(a[3]), "r"(b0), "r"(b1));
}

// ---------------- fp32 -> bf16 hi/lo split ----------------------------------
__device__ __forceinline__ void split4(
    const float* __restrict__ X, __nv_bfloat16* __restrict__ Hi,
    __nv_bfloat16* __restrict__ Lo, int i)
{
    float4 x = ((const float4*)X)[i];
    __nv_bfloat16 h0 = __float2bfloat16(x.x);
    __nv_bfloat16 h1 = __float2bfloat16(x.y);
    __nv_bfloat16 h2 = __float2bfloat16(x.z);
    __nv_bfloat16 h3 = __float2bfloat16(x.w);
    __nv_bfloat162 H0; H0.x = h0; H0.y = h1;
    __nv_bfloat162 H1; H1.x = h2; H1.y = h3;
    __nv_bfloat162 L0;
    L0.x = __float2bfloat16(x.x - __bfloat162float(h0));
    L0.y = __float2bfloat16(x.y - __bfloat162float(h1));
    __nv_bfloat162 L1;
    L1.x = __float2bfloat16(x.z - __bfloat162float(h2));
    L1.y = __float2bfloat16(x.w - __bfloat162float(h3));
    ((__nv_bfloat162*)Hi)[2 * i] = H0;
    ((__nv_bfloat162*)Hi)[2 * i + 1] = H1;
    ((__nv_bfloat162*)Lo)[2 * i] = L0;
    ((__nv_bfloat162*)Lo)[2 * i + 1] = L1;
}

__global__ __launch_bounds__(256) void split_act3_kernel(
    const float* __restrict__ X0, const float* __restrict__ X1,
    const float* __restrict__ X2, __nv_bfloat16* __restrict__ Hi,
    __nv_bfloat16* __restrict__ Lo, int n4)
{
    int i = blockIdx.x * 256 + threadIdx.x;
    if (i >= n4) return;
    int s = blockIdx.y;
    const float* X = (s == 0) ? X0 : (s == 1) ? X1 : X2;
    split4(X, Hi + (size_t)s * BATCH * SEQ * EMB,
           Lo + (size_t)s * BATCH * SEQ * EMB, i);
}

__global__ __launch_bounds__(256) void split_w4_kernel(
    const float* __restrict__ W0, const float* __restrict__ W1,
    const float* __restrict__ W2, const float* __restrict__ W3,
    __nv_bfloat16* __restrict__ Hi, __nv_bfloat16* __restrict__ Lo, int n4)
{
    int i = blockIdx.x * 256 + threadIdx.x;
    if (i >= n4) return;
    int s = blockIdx.y;
    const float* W = (s == 0) ? W0 : (s == 1) ? W1 : (s == 2) ? W2 : W3;
    split4(W, Hi + (size_t)s * EMB * EMB, Lo + (size_t)s * EMB * EMB, i);
}

// ---------------- fused bf16x3 GEMM: 4 warps, warp tile 64x64 ----------------
#define BM 128
#define BN 128
#define BK 32
#define ASTR 40
#define BSTR 136
#define A_ELEM (BM * ASTR)
#define B_ELEM (BK * BSTR)
#define STAGE_ELEM (2 * A_ELEM + 2 * B_ELEM)
#define GEMM_SMEM (2 * STAGE_ELEM * (int)sizeof(__nv_bfloat16))

#define CP_ASYNC16(dst, src) \
    asm volatile("cp.async.cg.shared.global [%0], [%1], 16;\n" :: "r"(dst), "l"(src))
#define CP_COMMIT asm volatile("cp.async.commit_group;\n" ::)
#define CP_WAITG(n) asm volatile("cp.async.wait_group %0;\n" :: "n"(n))

__device__ __forceinline__ void gemm_core(
    const __nv_bfloat16* __restrict__ Ahi, const __nv_bfloat16* __restrict__ Alo,
    const __nv_bfloat16* __restrict__ Bhi, const __nv_bfloat16* __restrict__ Blo,
    const float* __restrict__ bias, float* __restrict__ C,
    __nv_bfloat16* __restrict__ Chi, __nv_bfloat16* __restrict__ Clo,
    int M, int N, int K)
{
    extern __shared__ __align__(16) __nv_bfloat16 smem[];

    const int tid = threadIdx.x;
    const int lane = tid & 31;
    const int wid = tid >> 5;
    const int wm = wid & 1;
    const int wn = wid >> 1;
    const int row0 = blockIdx.y * BM;
    const int col0 = blockIdx.x * BN;

    float acc[4][8][4];
#pragma unroll
    for (int i = 0; i < 4; i++)
#pragma unroll
        for (int j = 0; j < 8; j++)
#pragma unroll
            for (int r = 0; r < 4; r++) acc[i][j][r] = 0.f;

    const int TOT = K / BK;

#define LOAD_STAGE(IT, BUF) do {                                               \
    int k0_ = (IT) * BK;                                                       \
    __nv_bfloat16* sa_hi = smem + (BUF) * STAGE_ELEM;                          \
    __nv_bfloat16* sa_lo = sa_hi + A_ELEM;                                     \
    __nv_bfloat16* sb_hi = sa_lo + A_ELEM;                                     \
    __nv_bfloat16* sb_lo = sb_hi + B_ELEM;                                     \
    _Pragma("unroll")                                                          \
    for (int li = 0; li < 4; li++) {                                           \
        int idx = tid + li * 128;                                              \
        int ar = idx >> 2, ac = (idx & 3) * 8;                                 \
        int br = idx >> 4, bc = (idx & 15) * 8;                                \
        CP_ASYNC16((uint32_t)__cvta_generic_to_shared(&sa_hi[ar * ASTR + ac]), \
                   Ahi + (size_t)(row0 + ar) * K + k0_ + ac);                  \
        CP_ASYNC16((uint32_t)__cvta_generic_to_shared(&sa_lo[ar * ASTR + ac]), \
                   Alo + (size_t)(row0 + ar) * K + k0_ + ac);                  \
        CP_ASYNC16((uint32_t)__cvta_generic_to_shared(&sb_hi[br * BSTR + bc]), \
                   Bhi + (size_t)(k0_ + br) * N + col0 + bc);                  \
        CP_ASYNC16((uint32_t)__cvta_generic_to_shared(&sb_lo[br * BSTR + bc]), \
                   Blo + (size_t)(k0_ + br) * N + col0 + bc);                  \
    }                                                                          \
} while (0)

    LOAD_STAGE(0, 0); CP_COMMIT;

    for (int it = 0; it < TOT; it++) {
        const int buf = it & 1;
        if (it + 1 < TOT) {
            LOAD_STAGE(it + 1, (it + 1) & 1);
            CP_COMMIT;
            CP_WAITG(1);
        } else {
            CP_WAITG(0);
        }
        __syncthreads();

        const __nv_bfloat16* sa_hi = smem + buf * STAGE_ELEM;
        const __nv_bfloat16* sa_lo = sa_hi + A_ELEM;
        const __nv_bfloat16* sb_hi = sa_lo + A_ELEM;
        const __nv_bfloat16* sb_lo = sb_hi + B_ELEM;

#pragma unroll
        for (int ks = 0; ks < 2; ks++) {
            uint32_t ahi[4][4], alo[4][4], bhi[4][4], blo[4][4];
#pragma unroll
            for (int mi = 0; mi < 4; mi++) {
                int roff = (wm * 64 + mi * 16 + (lane & 15)) * ASTR +
                           ks * 16 + (lane >> 4) * 8;
                ldsm4(ahi[mi], &sa_hi[roff]);
                ldsm4(alo[mi], &sa_lo[roff]);
            }
#pragma unroll
            for (int bi = 0; bi < 4; bi++) {
                int boff = (ks * 16 + (lane & 15)) * BSTR +
                           wn * 64 + bi * 16 + (lane >> 4) * 8;
                ldsm4t(bhi[bi], &sb_hi[boff]);
                ldsm4t(blo[bi], &sb_lo[boff]);
            }
#pragma unroll
            for (int bi = 0; bi < 4; bi++)
#pragma unroll
                for (int p = 0; p < 2; p++)
#pragma unroll
                    for (int mi = 0; mi < 4; mi++)
                        mma_bf16(acc[mi][bi * 2 + p], ahi[mi],
                                 bhi[bi][p * 2], bhi[bi][p * 2 + 1]);
#pragma unroll
            for (int bi = 0; bi < 4; bi++)
#pragma unroll
                for (int p = 0; p < 2; p++)
#pragma unroll
                    for (int mi = 0; mi < 4; mi++)
                        mma_bf16(acc[mi][bi * 2 + p], ahi[mi],
                                 blo[bi][p * 2], blo[bi][p * 2 + 1]);
#pragma unroll
            for (int bi = 0; bi < 4; bi++)
#pragma unroll
                for (int p = 0; p < 2; p++)
#pragma unroll
                    for (int mi = 0; mi < 4; mi++)
                        mma_bf16(acc[mi][bi * 2 + p], alo[mi],
                                 bhi[bi][p * 2], bhi[bi][p * 2 + 1]);
        }
        __syncthreads();
    }

    const int g = lane >> 2;
    const int t = lane & 3;
#pragma unroll
    for (int ni = 0; ni < 8; ni++) {
        int col = col0 + wn * 64 + ni * 8 + t * 2;
        float b0 = bias[col], b1 = bias[col + 1];
#pragma unroll
        for (int mi = 0; mi < 4; mi++) {
            int row = row0 + wm * 64 + mi * 16 + g;
            float v00 = acc[mi][ni][0] + b0, v01 = acc[mi][ni][1] + b1;
            float v10 = acc[mi][ni][2] + b0, v11 = acc[mi][ni][3] + b1;
            if (Chi) {
                __nv_bfloat162 h0, l0, h1, l1;
                h0.x = __float2bfloat16(v00);
                h0.y = __float2bfloat16(v01);
                l0.x = __float2bfloat16(v00 - __bfloat162float(h0.x));
                l0.y = __float2bfloat16(v01 - __bfloat162float(h0.y));
                h1.x = __float2bfloat16(v10);
                h1.y = __float2bfloat16(v11);
                l1.x = __float2bfloat16(v10 - __bfloat162float(h1.x));
                l1.y = __float2bfloat16(v11 - __bfloat162float(h1.y));
                *(__nv_bfloat162*)&Chi[(size_t)row * N + col] = h0;
                *(__nv_bfloat162*)&Clo[(size_t)row * N + col] = l0;
                *(__nv_bfloat162*)&Chi[(size_t)(row + 8) * N + col] = h1;
                *(__nv_bfloat162*)&Clo[(size_t)(row + 8) * N + col] = l1;
            } else {
                float2 o0 = { v00, v01 };
                float2 o1 = { v10, v11 };
                *(float2*)&C[(size_t)row * N + col] = o0;
                *(float2*)&C[(size_t)(row + 8) * N + col] = o1;
            }
        }
    }
#undef LOAD_STAGE
}

__global__ __launch_bounds__(128, 2) void gemm_qkv(
    const __nv_bfloat16* __restrict__ Ahi, const __nv_bfloat16* __restrict__ Alo,
    const __nv_bfloat16* __restrict__ Whi, const __nv_bfloat16* __restrict__ Wlo,
    const float* __restrict__ b0, const float* __restrict__ b1,
    const float* __restrict__ b2,
    __nv_bfloat16* __restrict__ o0h, __nv_bfloat16* __restrict__ o0l,
    __nv_bfloat16* __restrict__ o1h, __nv_bfloat16* __restrict__ o1l,
    __nv_bfloat16* __restrict__ o2h, __nv_bfloat16* __restrict__ o2l)
{
    const int s = blockIdx.z;
    const size_t AE = (size_t)BATCH * SEQ * EMB;
    const size_t WE = (size_t)EMB * EMB;
    const float* bias = (s == 0) ? b0 : (s == 1) ? b1 : b2;
    __nv_bfloat16* ch = (s == 0) ? o0h : (s == 1) ? o1h : o2h;
    __nv_bfloat16* cl = (s == 0) ? o0l : (s == 1) ? o1l : o2l;
    gemm_core(Ahi + s * AE, Alo + s * AE, Whi + s * WE, Wlo + s * WE,
              bias, nullptr, ch, cl, BATCH * SEQ, EMB, EMB);
}

__global__ __launch_bounds__(128, 2) void gemm_single(
    const __nv_bfloat16* __restrict__ Ahi, const __nv_bfloat16* __restrict__ Alo,
    const __nv_bfloat16* __restrict__ Whi, const __nv_bfloat16* __restrict__ Wlo,
    const float* __restrict__ bias, float* __restrict__ C)
{
    gemm_core(Ahi, Alo, Whi, Wlo, bias, C, nullptr, nullptr,
              BATCH * SEQ, EMB, EMB);
}

// ---------------- cw = softmax(query @ Wc + bc, axis=H) --------------------
// Wc transposed into smem (contiguous in k per h), q broadcast float4 reads.
// Thread = (row, h, khalf); 8 rows/block, 2 CTAs/SM.
#define WCT_STR 1026   // 16 h-lanes -> 16 distinct banks (2h mod 32 distinct)
#define CW_SMEM ((16 * WCT_STR + 8 * 1024) * (int)sizeof(float))

__global__ __launch_bounds__(256, 2) void cw_kernel(
    const float* __restrict__ query, const float* __restrict__ Wc,
    const float* __restrict__ bc, float* __restrict__ CW)
{
    extern __shared__ float csm[];
    float* wct = csm;                    // [16][WCT_STR]
    float* qs = csm + 16 * WCT_STR;      // [8][1024]
    const int tid = threadIdx.x;
    const int row0 = blockIdx.x * 8;

    // Wc transpose: linear read (coalesced), strided smem write
    for (int idx = tid; idx < 16384; idx += 256) {
        int k = idx >> 4, hh = idx & 15;
        wct[hh * WCT_STR + k] = Wc[idx];
    }
    // q rows: 2048 float4
    for (int idx = tid; idx < 2048; idx += 256) {
        int r = idx >> 8;
        int c4 = (idx & 255) * 4;
        *(float4*)&qs[r * 1024 + c4] = *(const float4*)&query[(size_t)(row0 + r) * EMB + c4];
    }
    __syncthreads();

    const int r = tid >> 5;          // warp = row
    const int lane = tid & 31;
    const int h = lane & 15;
    const int ks = lane >> 4;        // K half
    const float* q = &qs[r * 1024 + ks * 512];
    const float* wr = &wct[h * WCT_STR + ks * 512];

    float a0 = 0.f, a1 = 0.f, a2 = 0.f, a3 = 0.f;
#pragma unroll 8
    for (int i = 0; i < 512; i += 4) {
        float4 qv = *(const float4*)&q[i];   // broadcast across 16 h-lanes
        a0 += qv.x * wr[i + 0];
        a1 += qv.y * wr[i + 1];
        a2 += qv.z * wr[i + 2];
        a3 += qv.w * wr[i + 3];
    }
    float acc = (a0 + a1) + (a2 + a3);
    acc += __shfl_xor_sync(0xffffffffu, acc, 16);   // combine K halves
    acc += bc[h];

    float m = acc;
#pragma unroll
    for (int o = 8; o > 0; o >>= 1) m = fmaxf(m, __shfl_xor_sync(0xffffffffu, m, o, 16));
    float e = fast_exp(acc - m);
    float s = e;
#pragma unroll
    for (int o = 8; o > 0; o >>= 1) s += __shfl_xor_sync(0xffffffffu, s, o, 16);
    if (ks == 0) CW[(size_t)(row0 + r) * NH + h] = e / s;
}

// ---------------- suffix sums of V (bf16 hi/lo) -------------------------------
__global__ __launch_bounds__(256) void vsuffix_hl_kernel(
    const __nv_bfloat16* __restrict__ Vhi, const __nv_bfloat16* __restrict__ Vlo,
    float* __restrict__ Suf)
{
    __shared__ float T[4][64];
    const int bh = blockIdx.x;
    const int b = bh >> 4;
    const int h = bh & 15;
    const int t = threadIdx.x;
    const int p = t >> 6;
    const int d = t & 63;

    const size_t base = (size_t)b * SEQ * EMB + h * HD + d;
    float* sufb = Suf + (size_t)bh * SEQ * HD + d;

    const int k0 = p * 256;
    float s = 0.f;
#pragma unroll 4
    for (int k = k0; k < k0 + 256; k++) {
        size_t o = base + (size_t)k * EMB;
        s += __bfloat162float(Vhi[o]) + __bfloat162float(Vlo[o]);
    }
    T[p][d] = s;
    __syncthreads();

    float acc = 0.f;
    for (int pp = p + 1; pp < 4; pp++) acc += T[pp][d];
    for (int k = k0 + 252; k >= k0; k -= 4) {
        size_t o3 = base + (size_t)(k + 3) * EMB;
        size_t o2 = base + (size_t)(k + 2) * EMB;
        size_t o1 = base + (size_t)(k + 1) * EMB;
        size_t o0 = base + (size_t)(k + 0) * EMB;
        float v3 = __bfloat162float(Vhi[o3]) + __bfloat162float(Vlo[o3]);
        float v2 = __bfloat162float(Vhi[o2]) + __bfloat162float(Vlo[o2]);
        float v1 = __bfloat162float(Vhi[o1]) + __bfloat162float(Vlo[o1]);
        float v0 = __bfloat162float(Vhi[o0]) + __bfloat162float(Vlo[o0]);
        sufb[(size_t)(k + 3) * HD] = acc; acc += v3;
        sufb[(size_t)(k + 2) * HD] = acc; acc += v2;
        sufb[(size_t)(k + 1) * HD] = acc; acc += v1;
        sufb[(size_t)(k + 0) * HD] = acc; acc += v0;
    }
}

// ---------------- tensor-core attention --------------------------------------
#define AR 32
#define QSS 72
#define WSS 136
#define EST 1036
#define ESC_BYTES (AR * EST * 4)
#define KV_OFF    ESC_BYTES
#define KV_BYTES  (128 * QSS * 2)
#define QH_OFF    (KV_OFF + 2 * KV_BYTES)
#define QMAT_BYTES (AR * QSS * 2)
#define WH_OFF    (QH_OFF + 2 * QMAT_BYTES)
#define WMAT_BYTES (AR * WSS * 2)
#define ATTN_SMEM (WH_OFF + 2 * WMAT_BYTES)

__device__ __forceinline__ void stage_kv128(
    const __nv_bfloat16* __restrict__ Ghi, const __nv_bfloat16* __restrict__ Glo,
    __nv_bfloat16* s_hi, __nv_bfloat16* s_lo, int b, int h, int kt, int tid)
{
#pragma unroll
    for (int li = 0; li < 4; li++) {
        int c = tid + li * 256;
        int r = c >> 3, c16 = c & 7;
        size_t goff = (size_t)(b * SEQ + kt + r) * EMB + h * HD + c16 * 8;
        CP_ASYNC16((uint32_t)__cvta_generic_to_shared(s_hi + r * QSS + c16 * 8), Ghi + goff);
        CP_ASYNC16((uint32_t)__cvta_generic_to_shared(s_lo + r * QSS + c16 * 8), Glo + goff);
    }
}

__global__ __launch_bounds__(256, 1) void attn_mma_kernel(
    const __nv_bfloat16* __restrict__ Qhi, const __nv_bfloat16* __restrict__ Qlo,
    const __nv_bfloat16* __restrict__ Khi, const __nv_bfloat16* __restrict__ Klo,
    const __nv_bfloat16* __restrict__ Vhi, const __nv_bfloat16* __restrict__ Vlo,
    const float* __restrict__ CW, const float* __restrict__ cons,
    const float* __restrict__ Suf, float* __restrict__ attn_out,
    __nv_bfloat16* __restrict__ Chi, __nv_bfloat16* __restrict__ Clo)
{
    extern __shared__ __align__(16) char smraw[];
    float* esc = (float*)smraw;
    __nv_bfloat16* kv_hi = (__nv_bfloat16*)(smraw + KV_OFF);
    __nv_bfloat16* kv_lo = (__nv_bfloat16*)(smraw + KV_OFF + KV_BYTES);
    __nv_bfloat16* q_hi  = (__nv_bfloat16*)(smraw + QH_OFF);
    __nv_bfloat16* q_lo  = (__nv_bfloat16*)(smraw + QH_OFF + QMAT_BYTES);
    __nv_bfloat16* w_hi  = (__nv_bfloat16*)(smraw + WH_OFF);
    __nv_bfloat16* w_lo  = (__nv_bfloat16*)(smraw + WH_OFF + WMAT_BYTES);
    __shared__ float zinv[AR];

    const int tid = threadIdx.x;
    const int lane = tid & 31;
    const int w = tid >> 5;
    const int bh = blockIdx.y;
    const int b = bh >> 4;
    const int h = bh & 15;
    const int q0 = (gridDim.x - 1 - blockIdx.x) * AR;
    const int kmax = q0 + AR;
    const int ntiles = (kmax + 127) >> 7;
    const float INV_SCALE = 1.0f / (8.0f * sqrtf(1.61803398874989485f));

#pragma unroll
    for (int li = 0; li < 2; li++) {
        int c = tid + li * 256;
        int r = (c & 255) >> 3;
        int c16 = c & 7;
        const __nv_bfloat16* src = ((c < 256) ? Qhi : Qlo)
            + (size_t)(b * SEQ + q0 + r) * EMB + h * HD + c16 * 8;
        __nv_bfloat16* dst = ((c < 256) ? q_hi : q_lo) + r * QSS + c16 * 8;
        CP_ASYNC16((uint32_t)__cvta_generic_to_shared(dst), src);
    }
    CP_COMMIT;
    stage_kv128(Khi, Klo, kv_hi, kv_lo, b, h, 0, tid);
    CP_COMMIT;

    CP_WAITG(1);
    __syncthreads();
    uint32_t qh[4][2][4], ql[4][2][4];
#pragma unroll
    for (int ks = 0; ks < 4; ks++) {
        const int arow = lane & 15;
        const int acol = ks * 16 + (lane >> 4) * 8;
#pragma unroll
        for (int m = 0; m < 2; m++) {
            ldsm4(qh[ks][m], q_hi + (m * 16 + arow) * QSS + acol);
            ldsm4(ql[ks][m], q_lo + (m * 16 + arow) * QSS + acol);
        }
    }

    for (int t = 0; t < ntiles; t++) {
        const int kt = t * 128;
        CP_WAITG(0);
        __syncthreads();

        uint32_t kh[4][4], kl[4][4];
#pragma unroll
        for (int ks = 0; ks < 4; ks++) {
            const int arow = lane & 15;
            const int acol = ks * 16 + (lane >> 4) * 8;
            ldsm4(kh[ks], kv_hi + (w * 16 + arow) * QSS + acol);
            ldsm4(kl[ks], kv_lo + (w * 16 + arow) * QSS + acol);
        }
        __syncthreads();
        if (t + 1 < ntiles) {
            stage_kv128(Khi, Klo, kv_hi, kv_lo, b, h, kt + 128, tid);
            CP_COMMIT;
        }

        float accs[2][2][4];
#pragma unroll
        for (int m = 0; m < 2; m++)
#pragma unroll
            for (int n = 0; n < 2; n++)
#pragma unroll
                for (int r = 0; r < 4; r++) accs[m][n][r] = 0.f;

#pragma unroll
        for (int ks = 0; ks < 4; ks++)
#pragma unroll
            for (int m = 0; m < 2; m++)
#pragma unroll
                for (int n8 = 0; n8 < 2; n8++)
                    mma_bf16(accs[m][n8], qh[ks][m], kh[ks][n8], kh[ks][n8 + 2]);
#pragma unroll
        for (int ks = 0; ks < 4; ks++)
#pragma unroll
            for (int m = 0; m < 2; m++)
#pragma unroll
                for (int n8 = 0; n8 < 2; n8++)
                    mma_bf16(accs[m][n8], qh[ks][m], kl[ks][n8], kl[ks][n8 + 2]);
#pragma unroll
        for (int ks = 0; ks < 4; ks++)
#pragma unroll
            for (int m = 0; m < 2; m++)
#pragma unroll
                for (int n8 = 0; n8 < 2; n8++)
                    mma_bf16(accs[m][n8], ql[ks][m], kh[ks][n8], kh[ks][n8 + 2]);

#pragma unroll
        for (int m = 0; m < 2; m++)
#pragma unroll
            for (int n8 = 0; n8 < 2; n8++) {
                int row = m * 16 + (lane >> 2);
                int col = kt + w * 16 + n8 * 8 + (lane & 3) * 2;
                float2 lo = { accs[m][n8][0] * INV_SCALE, accs[m][n8][1] * INV_SCALE };
                float2 hi = { accs[m][n8][2] * INV_SCALE, accs[m][n8][3] * INV_SCALE };
                *(float2*)&esc[row * EST + col] = lo;
                *(float2*)&esc[(row + 8) * EST + col] = hi;
            }
    }
    stage_kv128(Vhi, Vlo, kv_hi, kv_lo, b, h, 0, tid);
    CP_COMMIT;
    __syncthreads();

    // ---- softmax1 -> rescale -> softmax2 numerators ----
    {
#pragma unroll
        for (int rr = 0; rr < 4; rr++) {
            int r = w * 4 + rr;
            int q = q0 + r;
            int kc = q + 1;
            float* row = &esc[r * EST];

            float m = -1e30f;
            for (int k = lane; k < kc; k += 32) m = fmaxf(m, row[k]);
#pragma unroll
            for (int o = 16; o > 0; o >>= 1) m = fmaxf(m, __shfl_xor_sync(0xffffffffu, m, o));

            float s = 0.f;
            for (int k = lane; k < kc; k += 32) {
                float p = fast_exp(row[k] - m);
                row[k] = p;
                s += p;
            }
#pragma unroll
            for (int o = 16; o > 0; o >>= 1) s += __shfl_xor_sync(0xffffffffu, s, o);

            float cb = cons[b * SEQ + q];
            float cwv = CW[(size_t)(b * SEQ + q) * NH + h];
            float fs = (1.f + cb * cwv) / s;

            float z2 = 0.f;
            for (int k = lane; k < kc; k += 32) {
                float e = fast_exp(row[k] * fs);
                row[k] = e;
                z2 += e;
            }
#pragma unroll
            for (int o = 16; o > 0; o >>= 1) z2 += __shfl_xor_sync(0xffffffffu, z2, o);
            z2 += (float)(SEQ - kc);
            if (lane == 0) zinv[r] = 1.f / z2;
        }
    }
    __syncthreads();

    // ---- write final attn (streaming stores; k>q analytic = zinv) ----
    {
        const size_t abase = ((size_t)bh * SEQ + q0) * SEQ;
#pragma unroll 4
        for (int it = 0; it < AR; it++) {
            int idx4 = tid + it * 256;
            int r = idx4 >> 8;
            int c4 = (idx4 & 255) * 4;
            int q = q0 + r;
            float zi = zinv[r];
            float4 v;
            if (c4 + 3 <= q) {
                v = *(float4*)&esc[r * EST + c4];
                v.x *= zi; v.y *= zi; v.z *= zi; v.w *= zi;
            } else if (c4 > q) {
                v.x = zi; v.y = zi; v.z = zi; v.w = zi;
            } else {
                float4 e = *(float4*)&esc[r * EST + c4];
                v.x = (c4 + 0 <= q) ? e.x * zi : zi;
                v.y = (c4 + 1 <= q) ? e.y * zi : zi;
                v.z = (c4 + 2 <= q) ? e.z * zi : zi;
                v.w = (c4 + 3 <= q) ? e.w * zi : zi;
            }
            __stcs((float4*)&attn_out[abase + (size_t)r * SEQ + c4], v);
        }
    }
    __syncthreads();

    // ---- ctx phase: causal mask folded into the w-tile conversion ----
    const int wm = w & 1;
    const int wn = w >> 1;
    float acca[2][4], accb[2][4];
#pragma unroll
    for (int n = 0; n < 2; n++)
#pragma unroll
        for (int r = 0; r < 4; r++) { acca[n][r] = 0.f; accb[n][r] = 0.f; }

    for (int t = 0; t < ntiles; t++) {
        const int kt = t * 128;
#pragma unroll
        for (int e = 0; e < 16; e++) {
            int elem = tid + e * 256;
            int row = elem >> 7, col = elem & 127;
            float v = (kt + col <= q0 + row) ? esc[row * EST + kt + col] : 0.f;
            __nv_bfloat16 hv = __float2bfloat16(v);
            w_hi[row * WSS + col] = hv;
            w_lo[row * WSS + col] = __float2bfloat16(v - __bfloat162float(hv));
        }
        CP_WAITG(0);
        __syncthreads();

        uint32_t vh[8][4], vl[8][4], wh[8][4], wl[8][4];
#pragma unroll
        for (int ks = 0; ks < 8; ks++) {
            const int arow = lane & 15;
            const int ahalf = (lane >> 4) * 8;
            ldsm4t(vh[ks], kv_hi + (ks * 16 + arow) * QSS + wn * 16 + ahalf);
            ldsm4t(vl[ks], kv_lo + (ks * 16 + arow) * QSS + wn * 16 + ahalf);
            ldsm4(wh[ks], w_hi + (wm * 16 + arow) * WSS + ks * 16 + ahalf);
            ldsm4(wl[ks], w_lo + (wm * 16 + arow) * WSS + ks * 16 + ahalf);
        }
        __syncthreads();
        if (t + 1 < ntiles) {
            stage_kv128(Vhi, Vlo, kv_hi, kv_lo, b, h, kt + 128, tid);
            CP_COMMIT;
        }

#pragma unroll
        for (int ks = 0; ks < 8; ks++) {
            float (*acc)[4] = (ks & 1) ? accb : acca;
#pragma unroll
            for (int n8 = 0; n8 < 2; n8++)
                mma_bf16(acc[n8], wh[ks], vh[ks][n8 * 2], vh[ks][n8 * 2 + 1]);
        }
#pragma unroll
        for (int ks = 0; ks < 8; ks++) {
            float (*acc)[4] = (ks & 1) ? accb : acca;
#pragma unroll
            for (int n8 = 0; n8 < 2; n8++)
                mma_bf16(acc[n8], wh[ks], vl[ks][n8 * 2], vl[ks][n8 * 2 + 1]);
        }
#pragma unroll
        for (int ks = 0; ks < 8; ks++) {
            float (*acc)[4] = (ks & 1) ? accb : acca;
#pragma unroll
            for (int n8 = 0; n8 < 2; n8++)
                mma_bf16(acc[n8], wl[ks], vh[ks][n8 * 2], vh[ks][n8 * 2 + 1]);
        }
        __syncthreads();
    }

#pragma unroll
    for (int n8 = 0; n8 < 2; n8++) {
        int r0 = wm * 16 + (lane >> 2);
        int dc = wn * 16 + n8 * 8 + (lane & 3) * 2;
        float zi0 = zinv[r0];
        float zi8 = zinv[r0 + 8];
        float2 s0 = *(const float2*)&Suf[((size_t)bh * SEQ + q0 + r0) * HD + dc];
        float2 s8 = *(const float2*)&Suf[((size_t)bh * SEQ + q0 + r0 + 8) * HD + dc];
        float v00 = (acca[n8][0] + accb[n8][0] + s0.x) * zi0;
        float v01 = (acca[n8][1] + accb[n8][1] + s0.y) * zi0;
        float v10 = (acca[n8][2] + accb[n8][2] + s8.x) * zi8;
        float v11 = (acca[n8][3] + accb[n8][3] + s8.y) * zi8;
        __nv_bfloat162 h0, l0, h1, l1;
        h0.x = __float2bfloat16(v00); h0.y = __float2bfloat16(v01);
        l0.x = __float2bfloat16(v00 - __bfloat162float(h0.x));
        l0.y = __float2bfloat16(v01 - __bfloat162float(h0.y));
        h1.x = __float2bfloat16(v10); h1.y = __float2bfloat16(v11);
        l1.x = __float2bfloat16(v10 - __bfloat162float(h1.x));
        l1.y = __float2bfloat16(v11 - __bfloat162float(h1.y));
        size_t o0 = ((size_t)(b * SEQ + q0 + r0)) * EMB + h * HD + dc;
        size_t o8 = ((size_t)(b * SEQ + q0 + r0 + 8)) * EMB + h * HD + dc;
        *(__nv_bfloat162*)&Chi[o0] = h0;
        *(__nv_bfloat162*)&Clo[o0] = l0;
        *(__nv_bfloat162*)&Chi[o8] = h1;
        *(__nv_bfloat162*)&Clo[o8] = l1;
    }
}

// ---------------- launch ----------------------------------------------------
extern "C" void kernel_launch(void* const* d_in, const int* in_sizes, int n_in,
                              void* d_out, int out_size)
{
    const float* query = (const float*)d_in[0];
    const float* key   = (const float*)d_in[1];
    const float* value = (const float*)d_in[2];
    const float* cons  = (const float*)d_in[3];
    const float* Wq = (const float*)d_in[5];
    const float* bq = (const float*)d_in[6];
    const float* Wk = (const float*)d_in[7];
    const float* bk = (const float*)d_in[8];
    const float* Wv = (const float*)d_in[9];
    const float* bv = (const float*)d_in[10];
    const float* Wo = (const float*)d_in[11];
    const float* bo = (const float*)d_in[12];
    const float* Wc = (const float*)d_in[13];
    const float* bc = (const float*)d_in[14];

    float* qp; cudaGetSymbolAddress((void**)&qp, g_q);
    float* kp; cudaGetSymbolAddress((void**)&kp, g_k);
    float* vp; cudaGetSymbolAddress((void**)&vp, g_v);
    float* cp; cudaGetSymbolAddress((void**)&cp, g_ctx);
    float* cwp; cudaGetSymbolAddress((void**)&cwp, g_cw);
    float* sufp; cudaGetSymbolAddress((void**)&sufp, g_vsuf);
    __nv_bfloat16* ahi; cudaGetSymbolAddress((void**)&ahi, g_ahi);
    __nv_bfloat16* alo; cudaGetSymbolAddress((void**)&alo, g_alo);
    __nv_bfloat16* whi; cudaGetSymbolAddress((void**)&whi, g_whi);
    __nv_bfloat16* wlo; cudaGetSymbolAddress((void**)&wlo, g_wlo);

    const int M = BATCH * SEQ;
    const int A4 = M * EMB / 4;
    const int W4 = EMB * EMB / 4;
    const size_t AE = (size_t)M * EMB;
    const size_t WE = (size_t)EMB * EMB;

    __nv_bfloat16* qhi = (__nv_bfloat16*)qp;  __nv_bfloat16* qlo = qhi + AE;
    __nv_bfloat16* khi = (__nv_bfloat16*)kp;  __nv_bfloat16* klo = khi + AE;
    __nv_bfloat16* vhi = (__nv_bfloat16*)vp;  __nv_bfloat16* vlo = vhi + AE;
    __nv_bfloat16* chi = (__nv_bfloat16*)cp;  __nv_bfloat16* clo = chi + AE;

    float* out = (float*)d_out;
    float* attn_out = out + (size_t)BATCH * SEQ * EMB;

    cudaFuncSetAttribute(gemm_qkv, cudaFuncAttributeMaxDynamicSharedMemorySize, GEMM_SMEM);
    cudaFuncSetAttribute(gemm_single, cudaFuncAttributeMaxDynamicSharedMemorySize, GEMM_SMEM);
    cudaFuncSetAttribute(attn_mma_kernel, cudaFuncAttributeMaxDynamicSharedMemorySize, ATTN_SMEM);
    cudaFuncSetAttribute(cw_kernel, cudaFuncAttributeMaxDynamicSharedMemorySize, CW_SMEM);

    dim3 sa_grid((A4 + 255) / 256, 3);
    split_act3_kernel<<<sa_grid, 256>>>(query, key, value, ahi, alo, A4);
    dim3 sw_grid((W4 + 255) / 256, 4);
    split_w4_kernel<<<sw_grid, 256>>>(Wq, Wk, Wv, Wo, whi, wlo, W4);

    dim3 qkv_grid(EMB / BN, M / BM, 3);
    gemm_qkv<<<qkv_grid, 128, GEMM_SMEM>>>(
        ahi, alo, whi, wlo, bq, bk, bv,
        qhi, qlo, khi, klo, vhi, vlo);

    cw_kernel<<<M / 8, 256, CW_SMEM>>>(query, Wc, bc, cwp);
    vsuffix_hl_kernel<<<BATCH * NH, 256>>>(vhi, vlo, sufp);

    dim3 attn_grid(SEQ / AR, BATCH * NH);
    attn_mma_kernel<<<attn_grid, 256, ATTN_SMEM>>>(
        qhi, qlo, khi, klo, vhi, vlo, cwp, cons, sufp, attn_out, chi, clo);

    dim3 gemm_grid(EMB / BN, M / BM);
    gemm_single<<<gemm_grid, 128, GEMM_SMEM>>>(
        chi, clo, whi + 3 * WE, wlo + 3 * WE, bo, out);
}

// round 16
// speedup vs baseline: 1.0278x; 1.0278x over previous
#include <cuda_runtime.h>
#include <cuda_bf16.h>
#include <math.h>
#include <stdint.h>

#define EMB 1024
#define SEQ 1024
#define BATCH 4
#define NH 16
#define HD 64

// ---------------- scratch (device globals; no allocation allowed) ----------
__device__ float g_q[BATCH * SEQ * EMB];
__device__ float g_k[BATCH * SEQ * EMB];
__device__ float g_v[BATCH * SEQ * EMB];
__device__ float g_ctx[BATCH * SEQ * EMB];
__device__ float g_cw[BATCH * SEQ * NH];
__device__ float g_vsuf[BATCH * NH * SEQ * HD];
__device__ __nv_bfloat16 g_ahi[3][BATCH * SEQ * EMB];
__device__ __nv_bfloat16 g_alo[3][BATCH * SEQ * EMB];
__device__ __nv_bfloat16 g_whi[4][EMB * EMB];
__device__ __nv_bfloat16 g_wlo[4][EMB * EMB];

// ---------------- fast exp: FFMA-only ---------------------------------------
__device__ __forceinline__ float fast_exp(float x)
{
    x = fmaxf(x, -80.0f);
    const float L2E = 1.4426950408889634f;
    float t = fmaf(x, L2E, 12582912.0f);
    float i = t - 12582912.0f;
    float f = fmaf(x, L2E, -i);
    float p = 1.3333558146e-3f;
    p = fmaf(p, f, 9.6181291918e-3f);
    p = fmaf(p, f, 5.5504108664e-2f);
    p = fmaf(p, f, 2.4022650696e-1f);
    p = fmaf(p, f, 6.9314718056e-1f);
    p = fmaf(p, f, 1.0f);
    return __int_as_float(__float_as_int(p) + ((int)i << 23));
}

// ---------------- mma / ldmatrix helpers -------------------------------------
__device__ __forceinline__ void ldsm4(uint32_t* r, const void* p)
{
    uint32_t a = (uint32_t)__cvta_generic_to_shared(p);
    asm volatile("ldmatrix.sync.aligned.m8n8.x4.shared.b16 {%0,%1,%2,%3},[%4];"
                 : "=r"(r[0]), "=r"(r[1]), "=r"(r[2]), "=r"(r[3]) : "r"(a));
}
__device__ __forceinline__ void ldsm4t(uint32_t* r, const void* p)
{
    uint32_t a = (uint32_t)__cvta_generic_to_shared(p);
    asm volatile("ldmatrix.sync.aligned.m8n8.x4.trans.shared.b16 {%0,%1,%2,%3},[%4];"
                 : "=r"(r[0]), "=r"(r[1]), "=r"(r[2]), "=r"(r[3]) : "r"(a));
}
__device__ __forceinline__ void mma_bf16(float* c, const uint32_t* a,
                                         uint32_t b0, uint32_t b1)
{
    asm("mma.sync.aligned.m16n8k16.row.col.f32.bf16.bf16.f32 "
        "{%0,%1,%2,%3},{%4,%5,%6,%7},{%8,%9},{%0,%1,%2,%3};"
        : "+f"(c[0]), "+f"(c[1]), "+f"(c[2]), "+f"(c[3])
        : "r"(a[0]), "r"(a[1]), "r"(a[2]), "r"(a[3]), "r"(b0), "r"(b1));
}

// ---------------- fp32 -> bf16 hi/lo split ----------------------------------
__device__ __forceinline__ void split4(
    const float* __restrict__ X, __nv_bfloat16* __restrict__ Hi,
    __nv_bfloat16* __restrict__ Lo, int i)
{
    float4 x = ((const float4*)X)[i];
    __nv_bfloat16 h0 = __float2bfloat16(x.x);
    __nv_bfloat16 h1 = __float2bfloat16(x.y);
    __nv_bfloat16 h2 = __float2bfloat16(x.z);
    __nv_bfloat16 h3 = __float2bfloat16(x.w);
    __nv_bfloat162 H0; H0.x = h0; H0.y = h1;
    __nv_bfloat162 H1; H1.x = h2; H1.y = h3;
    __nv_bfloat162 L0;
    L0.x = __float2bfloat16(x.x - __bfloat162float(h0));
    L0.y = __float2bfloat16(x.y - __bfloat162float(h1));
    __nv_bfloat162 L1;
    L1.x = __float2bfloat16(x.z - __bfloat162float(h2));
    L1.y = __float2bfloat16(x.w - __bfloat162float(h3));
    ((__nv_bfloat162*)Hi)[2 * i] = H0;
    ((__nv_bfloat162*)Hi)[2 * i + 1] = H1;
    ((__nv_bfloat162*)Lo)[2 * i] = L0;
    ((__nv_bfloat162*)Lo)[2 * i + 1] = L1;
}

__global__ __launch_bounds__(256) void split_act3_kernel(
    const float* __restrict__ X0, const float* __restrict__ X1,
    const float* __restrict__ X2, __nv_bfloat16* __restrict__ Hi,
    __nv_bfloat16* __restrict__ Lo, int n4)
{
    int i = blockIdx.x * 256 + threadIdx.x;
    if (i >= n4) return;
    int s = blockIdx.y;
    const float* X = (s == 0) ? X0 : (s == 1) ? X1 : X2;
    split4(X, Hi + (size_t)s * BATCH * SEQ * EMB,
           Lo + (size_t)s * BATCH * SEQ * EMB, i);
}

__global__ __launch_bounds__(256) void split_w4_kernel(
    const float* __restrict__ W0, const float* __restrict__ W1,
    const float* __restrict__ W2, const float* __restrict__ W3,
    __nv_bfloat16* __restrict__ Hi, __nv_bfloat16* __restrict__ Lo, int n4)
{
    int i = blockIdx.x * 256 + threadIdx.x;
    if (i >= n4) return;
    int s = blockIdx.y;
    const float* W = (s == 0) ? W0 : (s == 1) ? W1 : (s == 2) ? W2 : W3;
    split4(W, Hi + (size_t)s * EMB * EMB, Lo + (size_t)s * EMB * EMB, i);
}

// ---------------- fused bf16x3 GEMM: 4 warps, warp tile 64x64 ----------------
#define BM 128
#define BN 128
#define BK 32
#define ASTR 40
#define BSTR 136
#define A_ELEM (BM * ASTR)
#define B_ELEM (BK * BSTR)
#define STAGE_ELEM (2 * A_ELEM + 2 * B_ELEM)
#define GEMM_SMEM (2 * STAGE_ELEM * (int)sizeof(__nv_bfloat16))

#define CP_ASYNC16(dst, src) \
    asm volatile("cp.async.cg.shared.global [%0], [%1], 16;\n" :: "r"(dst), "l"(src))
#define CP_COMMIT asm volatile("cp.async.commit_group;\n" ::)
#define CP_WAITG(n) asm volatile("cp.async.wait_group %0;\n" :: "n"(n))

__device__ __forceinline__ void gemm_core(
    const __nv_bfloat16* __restrict__ Ahi, const __nv_bfloat16* __restrict__ Alo,
    const __nv_bfloat16* __restrict__ Bhi, const __nv_bfloat16* __restrict__ Blo,
    const float* __restrict__ bias, float* __restrict__ C,
    __nv_bfloat16* __restrict__ Chi, __nv_bfloat16* __restrict__ Clo,
    int M, int N, int K)
{
    extern __shared__ __align__(16) __nv_bfloat16 smem[];

    const int tid = threadIdx.x;
    const int lane = tid & 31;
    const int wid = tid >> 5;
    const int wm = wid & 1;
    const int wn = wid >> 1;
    const int row0 = blockIdx.y * BM;
    const int col0 = blockIdx.x * BN;

    float acc[4][8][4];
#pragma unroll
    for (int i = 0; i < 4; i++)
#pragma unroll
        for (int j = 0; j < 8; j++)
#pragma unroll
            for (int r = 0; r < 4; r++) acc[i][j][r] = 0.f;

    const int TOT = K / BK;

#define LOAD_STAGE(IT, BUF) do {                                               \
    int k0_ = (IT) * BK;                                                       \
    __nv_bfloat16* sa_hi = smem + (BUF) * STAGE_ELEM;                          \
    __nv_bfloat16* sa_lo = sa_hi + A_ELEM;                                     \
    __nv_bfloat16* sb_hi = sa_lo + A_ELEM;                                     \
    __nv_bfloat16* sb_lo = sb_hi + B_ELEM;                                     \
    _Pragma("unroll")                                                          \
    for (int li = 0; li < 4; li++) {                                           \
        int idx = tid + li * 128;                                              \
        int ar = idx >> 2, ac = (idx & 3) * 8;                                 \
        int br = idx >> 4, bc = (idx & 15) * 8;                                \
        CP_ASYNC16((uint32_t)__cvta_generic_to_shared(&sa_hi[ar * ASTR + ac]), \
                   Ahi + (size_t)(row0 + ar) * K + k0_ + ac);                  \
        CP_ASYNC16((uint32_t)__cvta_generic_to_shared(&sa_lo[ar * ASTR + ac]), \
                   Alo + (size_t)(row0 + ar) * K + k0_ + ac);                  \
        CP_ASYNC16((uint32_t)__cvta_generic_to_shared(&sb_hi[br * BSTR + bc]), \
                   Bhi + (size_t)(k0_ + br) * N + col0 + bc);                  \
        CP_ASYNC16((uint32_t)__cvta_generic_to_shared(&sb_lo[br * BSTR + bc]), \
                   Blo + (size_t)(k0_ + br) * N + col0 + bc);                  \
    }                                                                          \
} while (0)

    LOAD_STAGE(0, 0); CP_COMMIT;

    for (int it = 0; it < TOT; it++) {
        const int buf = it & 1;
        if (it + 1 < TOT) {
            LOAD_STAGE(it + 1, (it + 1) & 1);
            CP_COMMIT;
            CP_WAITG(1);
        } else {
            CP_WAITG(0);
        }
        __syncthreads();

        const __nv_bfloat16* sa_hi = smem + buf * STAGE_ELEM;
        const __nv_bfloat16* sa_lo = sa_hi + A_ELEM;
        const __nv_bfloat16* sb_hi = sa_lo + A_ELEM;
        const __nv_bfloat16* sb_lo = sb_hi + B_ELEM;

#pragma unroll
        for (int ks = 0; ks < 2; ks++) {
            uint32_t ahi[4][4], alo[4][4], bhi[4][4], blo[4][4];
#pragma unroll
            for (int mi = 0; mi < 4; mi++) {
                int roff = (wm * 64 + mi * 16 + (lane & 15)) * ASTR +
                           ks * 16 + (lane >> 4) * 8;
                ldsm4(ahi[mi], &sa_hi[roff]);
                ldsm4(alo[mi], &sa_lo[roff]);
            }
#pragma unroll
            for (int bi = 0; bi < 4; bi++) {
                int boff = (ks * 16 + (lane & 15)) * BSTR +
                           wn * 64 + bi * 16 + (lane >> 4) * 8;
                ldsm4t(bhi[bi], &sb_hi[boff]);
                ldsm4t(blo[bi], &sb_lo[boff]);
            }
#pragma unroll
            for (int bi = 0; bi < 4; bi++)
#pragma unroll
                for (int p = 0; p < 2; p++)
#pragma unroll
                    for (int mi = 0; mi < 4; mi++)
                        mma_bf16(acc[mi][bi * 2 + p], ahi[mi],
                                 bhi[bi][p * 2], bhi[bi][p * 2 + 1]);
#pragma unroll
            for (int bi = 0; bi < 4; bi++)
#pragma unroll
                for (int p = 0; p < 2; p++)
#pragma unroll
                    for (int mi = 0; mi < 4; mi++)
                        mma_bf16(acc[mi][bi * 2 + p], ahi[mi],
                                 blo[bi][p * 2], blo[bi][p * 2 + 1]);
#pragma unroll
            for (int bi = 0; bi < 4; bi++)
#pragma unroll
                for (int p = 0; p < 2; p++)
#pragma unroll
                    for (int mi = 0; mi < 4; mi++)
                        mma_bf16(acc[mi][bi * 2 + p], alo[mi],
                                 bhi[bi][p * 2], bhi[bi][p * 2 + 1]);
        }
        __syncthreads();
    }

    const int g = lane >> 2;
    const int t = lane & 3;
#pragma unroll
    for (int ni = 0; ni < 8; ni++) {
        int col = col0 + wn * 64 + ni * 8 + t * 2;
        float b0 = bias[col], b1 = bias[col + 1];
#pragma unroll
        for (int mi = 0; mi < 4; mi++) {
            int row = row0 + wm * 64 + mi * 16 + g;
            float v00 = acc[mi][ni][0] + b0, v01 = acc[mi][ni][1] + b1;
            float v10 = acc[mi][ni][2] + b0, v11 = acc[mi][ni][3] + b1;
            if (Chi) {
                __nv_bfloat162 h0, l0, h1, l1;
                h0.x = __float2bfloat16(v00);
                h0.y = __float2bfloat16(v01);
                l0.x = __float2bfloat16(v00 - __bfloat162float(h0.x));
                l0.y = __float2bfloat16(v01 - __bfloat162float(h0.y));
                h1.x = __float2bfloat16(v10);
                h1.y = __float2bfloat16(v11);
                l1.x = __float2bfloat16(v10 - __bfloat162float(h1.x));
                l1.y = __float2bfloat16(v11 - __bfloat162float(h1.y));
                *(__nv_bfloat162*)&Chi[(size_t)row * N + col] = h0;
                *(__nv_bfloat162*)&Clo[(size_t)row * N + col] = l0;
                *(__nv_bfloat162*)&Chi[(size_t)(row + 8) * N + col] = h1;
                *(__nv_bfloat162*)&Clo[(size_t)(row + 8) * N + col] = l1;
            } else {
                float2 o0 = { v00, v01 };
                float2 o1 = { v10, v11 };
                *(float2*)&C[(size_t)row * N + col] = o0;
                *(float2*)&C[(size_t)(row + 8) * N + col] = o1;
            }
        }
    }
#undef LOAD_STAGE
}

__global__ __launch_bounds__(128, 2) void gemm_qkv(
    const __nv_bfloat16* __restrict__ Ahi, const __nv_bfloat16* __restrict__ Alo,
    const __nv_bfloat16* __restrict__ Whi, const __nv_bfloat16* __restrict__ Wlo,
    const float* __restrict__ b0, const float* __restrict__ b1,
    const float* __restrict__ b2,
    __nv_bfloat16* __restrict__ o0h, __nv_bfloat16* __restrict__ o0l,
    __nv_bfloat16* __restrict__ o1h, __nv_bfloat16* __restrict__ o1l,
    __nv_bfloat16* __restrict__ o2h, __nv_bfloat16* __restrict__ o2l)
{
    const int s = blockIdx.z;
    const size_t AE = (size_t)BATCH * SEQ * EMB;
    const size_t WE = (size_t)EMB * EMB;
    const float* bias = (s == 0) ? b0 : (s == 1) ? b1 : b2;
    __nv_bfloat16* ch = (s == 0) ? o0h : (s == 1) ? o1h : o2h;
    __nv_bfloat16* cl = (s == 0) ? o0l : (s == 1) ? o1l : o2l;
    gemm_core(Ahi + s * AE, Alo + s * AE, Whi + s * WE, Wlo + s * WE,
              bias, nullptr, ch, cl, BATCH * SEQ, EMB, EMB);
}

__global__ __launch_bounds__(128, 2) void gemm_single(
    const __nv_bfloat16* __restrict__ Ahi, const __nv_bfloat16* __restrict__ Alo,
    const __nv_bfloat16* __restrict__ Whi, const __nv_bfloat16* __restrict__ Wlo,
    const float* __restrict__ bias, float* __restrict__ C)
{
    gemm_core(Ahi, Alo, Whi, Wlo, bias, C, nullptr, nullptr,
              BATCH * SEQ, EMB, EMB);
}

// ---------------- cw = softmax(query @ Wc + bc, axis=H) --------------------
// (round-14 version: 30 us, best measured)
__global__ __launch_bounds__(256) void cw_kernel(
    const float* __restrict__ query, const float* __restrict__ Wc,
    const float* __restrict__ bc, float* __restrict__ CW)
{
    __shared__ float qs[8][1024];
    const int tid = threadIdx.x;
    const int row0 = blockIdx.x * 8;

    for (int idx = tid; idx < 2048; idx += 256) {
        int r = idx >> 8;
        int c4 = (idx & 255) * 4;
        *(float4*)&qs[r][c4] = *(const float4*)&query[(size_t)(row0 + r) * EMB + c4];
    }
    __syncthreads();

    const int lane = tid & 31;
    const int r = tid >> 5;
    const int h = lane & 15;
    const int ks = lane >> 4;
    const float* q = &qs[r][ks * 512];
    const float* wc = &Wc[(size_t)(ks * 512) * NH + h];

    float a0 = 0.f, a1 = 0.f, a2 = 0.f, a3 = 0.f;
#pragma unroll 4
    for (int i = 0; i < 512; i += 4) {
        float4 qv = *(const float4*)&q[i];
        a0 += qv.x * wc[(i + 0) * NH];
        a1 += qv.y * wc[(i + 1) * NH];
        a2 += qv.z * wc[(i + 2) * NH];
        a3 += qv.w * wc[(i + 3) * NH];
    }
    float acc = (a0 + a1) + (a2 + a3);
    acc += __shfl_xor_sync(0xffffffffu, acc, 16);
    acc += bc[h];

    float m = acc;
#pragma unroll
    for (int o = 8; o > 0; o >>= 1) m = fmaxf(m, __shfl_xor_sync(0xffffffffu, m, o, 16));
    float e = fast_exp(acc - m);
    float s = e;
#pragma unroll
    for (int o = 8; o > 0; o >>= 1) s += __shfl_xor_sync(0xffffffffu, s, o, 16);
    if (ks == 0) CW[(size_t)(row0 + r) * NH + h] = e / s;
}

// ---------------- suffix sums of V (bf16 hi/lo) -------------------------------
__global__ __launch_bounds__(256) void vsuffix_hl_kernel(
    const __nv_bfloat16* __restrict__ Vhi, const __nv_bfloat16* __restrict__ Vlo,
    float* __restrict__ Suf)
{
    __shared__ float T[4][64];
    const int bh = blockIdx.x;
    const int b = bh >> 4;
    const int h = bh & 15;
    const int t = threadIdx.x;
    const int p = t >> 6;
    const int d = t & 63;

    const size_t base = (size_t)b * SEQ * EMB + h * HD + d;
    float* sufb = Suf + (size_t)bh * SEQ * HD + d;

    const int k0 = p * 256;
    float s = 0.f;
#pragma unroll 4
    for (int k = k0; k < k0 + 256; k++) {
        size_t o = base + (size_t)k * EMB;
        s += __bfloat162float(Vhi[o]) + __bfloat162float(Vlo[o]);
    }
    T[p][d] = s;
    __syncthreads();

    float acc = 0.f;
    for (int pp = p + 1; pp < 4; pp++) acc += T[pp][d];
    for (int k = k0 + 252; k >= k0; k -= 4) {
        size_t o3 = base + (size_t)(k + 3) * EMB;
        size_t o2 = base + (size_t)(k + 2) * EMB;
        size_t o1 = base + (size_t)(k + 1) * EMB;
        size_t o0 = base + (size_t)(k + 0) * EMB;
        float v3 = __bfloat162float(Vhi[o3]) + __bfloat162float(Vlo[o3]);
        float v2 = __bfloat162float(Vhi[o2]) + __bfloat162float(Vlo[o2]);
        float v1 = __bfloat162float(Vhi[o1]) + __bfloat162float(Vlo[o1]);
        float v0 = __bfloat162float(Vhi[o0]) + __bfloat162float(Vlo[o0]);
        sufb[(size_t)(k + 3) * HD] = acc; acc += v3;
        sufb[(size_t)(k + 2) * HD] = acc; acc += v2;
        sufb[(size_t)(k + 1) * HD] = acc; acc += v1;
        sufb[(size_t)(k + 0) * HD] = acc; acc += v0;
    }
}

// ---------------- tensor-core attention --------------------------------------
#define AR 32
#define QSS 72
#define WSS 136
#define EST 1036
#define ESC_BYTES (AR * EST * 4)
#define KV_OFF    ESC_BYTES
#define KV_BYTES  (128 * QSS * 2)
#define QH_OFF    (KV_OFF + 2 * KV_BYTES)
#define QMAT_BYTES (AR * QSS * 2)
#define WH_OFF    (QH_OFF + 2 * QMAT_BYTES)
#define WMAT_BYTES (AR * WSS * 2)
#define ATTN_SMEM (WH_OFF + 2 * WMAT_BYTES)

__device__ __forceinline__ void stage_kv128(
    const __nv_bfloat16* __restrict__ Ghi, const __nv_bfloat16* __restrict__ Glo,
    __nv_bfloat16* s_hi, __nv_bfloat16* s_lo, int b, int h, int kt, int tid)
{
#pragma unroll
    for (int li = 0; li < 4; li++) {
        int c = tid + li * 256;
        int r = c >> 3, c16 = c & 7;
        size_t goff = (size_t)(b * SEQ + kt + r) * EMB + h * HD + c16 * 8;
        CP_ASYNC16((uint32_t)__cvta_generic_to_shared(s_hi + r * QSS + c16 * 8), Ghi + goff);
        CP_ASYNC16((uint32_t)__cvta_generic_to_shared(s_lo + r * QSS + c16 * 8), Glo + goff);
    }
}

__global__ __launch_bounds__(256, 1) void attn_mma_kernel(
    const __nv_bfloat16* __restrict__ Qhi, const __nv_bfloat16* __restrict__ Qlo,
    const __nv_bfloat16* __restrict__ Khi, const __nv_bfloat16* __restrict__ Klo,
    const __nv_bfloat16* __restrict__ Vhi, const __nv_bfloat16* __restrict__ Vlo,
    const float* __restrict__ CW, const float* __restrict__ cons,
    const float* __restrict__ Suf, float* __restrict__ attn_out,
    __nv_bfloat16* __restrict__ Chi, __nv_bfloat16* __restrict__ Clo)
{
    extern __shared__ __align__(16) char smraw[];
    float* esc = (float*)smraw;
    __nv_bfloat16* kv_hi = (__nv_bfloat16*)(smraw + KV_OFF);
    __nv_bfloat16* kv_lo = (__nv_bfloat16*)(smraw + KV_OFF + KV_BYTES);
    __nv_bfloat16* q_hi  = (__nv_bfloat16*)(smraw + QH_OFF);
    __nv_bfloat16* q_lo  = (__nv_bfloat16*)(smraw + QH_OFF + QMAT_BYTES);
    __nv_bfloat16* w_hi  = (__nv_bfloat16*)(smraw + WH_OFF);
    __nv_bfloat16* w_lo  = (__nv_bfloat16*)(smraw + WH_OFF + WMAT_BYTES);
    __shared__ float zinv[AR];

    const int tid = threadIdx.x;
    const int lane = tid & 31;
    const int w = tid >> 5;
    const int bh = blockIdx.y;
    const int b = bh >> 4;
    const int h = bh & 15;
    const int q0 = (gridDim.x - 1 - blockIdx.x) * AR;
    const int kmax = q0 + AR;
    const int ntiles = (kmax + 127) >> 7;
    const float INV_SCALE = 1.0f / (8.0f * sqrtf(1.61803398874989485f));

#pragma unroll
    for (int li = 0; li < 2; li++) {
        int c = tid + li * 256;
        int r = (c & 255) >> 3;
        int c16 = c & 7;
        const __nv_bfloat16* src = ((c < 256) ? Qhi : Qlo)
            + (size_t)(b * SEQ + q0 + r) * EMB + h * HD + c16 * 8;
        __nv_bfloat16* dst = ((c < 256) ? q_hi : q_lo) + r * QSS + c16 * 8;
        CP_ASYNC16((uint32_t)__cvta_generic_to_shared(dst), src);
    }
    CP_COMMIT;
    stage_kv128(Khi, Klo, kv_hi, kv_lo, b, h, 0, tid);
    CP_COMMIT;

    CP_WAITG(1);
    __syncthreads();
    uint32_t qh[4][2][4], ql[4][2][4];
#pragma unroll
    for (int ks = 0; ks < 4; ks++) {
        const int arow = lane & 15;
        const int acol = ks * 16 + (lane >> 4) * 8;
#pragma unroll
        for (int m = 0; m < 2; m++) {
            ldsm4(qh[ks][m], q_hi + (m * 16 + arow) * QSS + acol);
            ldsm4(ql[ks][m], q_lo + (m * 16 + arow) * QSS + acol);
        }
    }

    for (int t = 0; t < ntiles; t++) {
        const int kt = t * 128;
        CP_WAITG(0);
        __syncthreads();

        uint32_t kh[4][4], kl[4][4];
#pragma unroll
        for (int ks = 0; ks < 4; ks++) {
            const int arow = lane & 15;
            const int acol = ks * 16 + (lane >> 4) * 8;
            ldsm4(kh[ks], kv_hi + (w * 16 + arow) * QSS + acol);
            ldsm4(kl[ks], kv_lo + (w * 16 + arow) * QSS + acol);
        }
        __syncthreads();
        if (t + 1 < ntiles) {
            stage_kv128(Khi, Klo, kv_hi, kv_lo, b, h, kt + 128, tid);
            CP_COMMIT;
        }

        float accs[2][2][4];
#pragma unroll
        for (int m = 0; m < 2; m++)
#pragma unroll
            for (int n = 0; n < 2; n++)
#pragma unroll
                for (int r = 0; r < 4; r++) accs[m][n][r] = 0.f;

#pragma unroll
        for (int ks = 0; ks < 4; ks++)
#pragma unroll
            for (int m = 0; m < 2; m++)
#pragma unroll
                for (int n8 = 0; n8 < 2; n8++)
                    mma_bf16(accs[m][n8], qh[ks][m], kh[ks][n8], kh[ks][n8 + 2]);
#pragma unroll
        for (int ks = 0; ks < 4; ks++)
#pragma unroll
            for (int m = 0; m < 2; m++)
#pragma unroll
                for (int n8 = 0; n8 < 2; n8++)
                    mma_bf16(accs[m][n8], qh[ks][m], kl[ks][n8], kl[ks][n8 + 2]);
#pragma unroll
        for (int ks = 0; ks < 4; ks++)
#pragma unroll
            for (int m = 0; m < 2; m++)
#pragma unroll
                for (int n8 = 0; n8 < 2; n8++)
                    mma_bf16(accs[m][n8], ql[ks][m], kh[ks][n8], kh[ks][n8 + 2]);

#pragma unroll
        for (int m = 0; m < 2; m++)
#pragma unroll
            for (int n8 = 0; n8 < 2; n8++) {
                int row = m * 16 + (lane >> 2);
                int col = kt + w * 16 + n8 * 8 + (lane & 3) * 2;
                float2 lo = { accs[m][n8][0] * INV_SCALE, accs[m][n8][1] * INV_SCALE };
                float2 hi = { accs[m][n8][2] * INV_SCALE, accs[m][n8][3] * INV_SCALE };
                *(float2*)&esc[row * EST + col] = lo;
                *(float2*)&esc[(row + 8) * EST + col] = hi;
            }
    }
    stage_kv128(Vhi, Vlo, kv_hi, kv_lo, b, h, 0, tid);
    CP_COMMIT;
    __syncthreads();

    // ---- softmax1 -> rescale -> softmax2 numerators + FUSED attn write ----
    {
        const size_t abase = ((size_t)bh * SEQ + q0) * SEQ;
#pragma unroll
        for (int rr = 0; rr < 4; rr++) {
            int r = w * 4 + rr;
            int q = q0 + r;
            int kc = q + 1;
            float* row = &esc[r * EST];

            float m = -1e30f;
            for (int k = lane; k < kc; k += 32) m = fmaxf(m, row[k]);
#pragma unroll
            for (int o = 16; o > 0; o >>= 1) m = fmaxf(m, __shfl_xor_sync(0xffffffffu, m, o));

            float s = 0.f;
            for (int k = lane; k < kc; k += 32) {
                float p = fast_exp(row[k] - m);
                row[k] = p;
                s += p;
            }
#pragma unroll
            for (int o = 16; o > 0; o >>= 1) s += __shfl_xor_sync(0xffffffffu, s, o);

            float cb = cons[b * SEQ + q];
            float cwv = CW[(size_t)(b * SEQ + q) * NH + h];
            float fs = (1.f + cb * cwv) / s;

            float z2 = 0.f;
            for (int k = lane; k < kc; k += 32) {
                float e = fast_exp(row[k] * fs);
                row[k] = e;
                z2 += e;
            }
#pragma unroll
            for (int o = 16; o > 0; o >>= 1) z2 += __shfl_xor_sync(0xffffffffu, z2, o);
            z2 += (float)(SEQ - kc);
            float zi = 1.f / z2;
            if (lane == 0) zinv[r] = zi;

            // fused attn write for this row (warp-parallel float4 stores)
            float* gout = &attn_out[abase + (size_t)r * SEQ];
            for (int c4 = lane * 4; c4 < SEQ; c4 += 128) {
                float4 v;
                if (c4 + 3 <= q) {
                    v = *(float4*)&row[c4];
                    v.x *= zi; v.y *= zi; v.z *= zi; v.w *= zi;
                } else if (c4 > q) {
                    v.x = zi; v.y = zi; v.z = zi; v.w = zi;
                } else {
                    float4 e = *(float4*)&row[c4];
                    v.x = (c4 + 0 <= q) ? e.x * zi : zi;
                    v.y = (c4 + 1 <= q) ? e.y * zi : zi;
                    v.z = (c4 + 2 <= q) ? e.z * zi : zi;
                    v.w = (c4 + 3 <= q) ? e.w * zi : zi;
                }
                __stcs((float4*)&gout[c4], v);
            }
        }
    }
    __syncthreads();

    // ---- ctx phase: causal mask folded into the w-tile conversion ----
    const int wm = w & 1;
    const int wn = w >> 1;
    float acca[2][4], accb[2][4];
#pragma unroll
    for (int n = 0; n < 2; n++)
#pragma unroll
        for (int r = 0; r < 4; r++) { acca[n][r] = 0.f; accb[n][r] = 0.f; }

    for (int t = 0; t < ntiles; t++) {
        const int kt = t * 128;
#pragma unroll
        for (int e = 0; e < 16; e++) {
            int elem = tid + e * 256;
            int row = elem >> 7, col = elem & 127;
            float v = (kt + col <= q0 + row) ? esc[row * EST + kt + col] : 0.f;
            __nv_bfloat16 hv = __float2bfloat16(v);
            w_hi[row * WSS + col] = hv;
            w_lo[row * WSS + col] = __float2bfloat16(v - __bfloat162float(hv));
        }
        CP_WAITG(0);
        __syncthreads();

        uint32_t vh[8][4], vl[8][4], wh[8][4], wl[8][4];
#pragma unroll
        for (int ks = 0; ks < 8; ks++) {
            const int arow = lane & 15;
            const int ahalf = (lane >> 4) * 8;
            ldsm4t(vh[ks], kv_hi + (ks * 16 + arow) * QSS + wn * 16 + ahalf);
            ldsm4t(vl[ks], kv_lo + (ks * 16 + arow) * QSS + wn * 16 + ahalf);
            ldsm4(wh[ks], w_hi + (wm * 16 + arow) * WSS + ks * 16 + ahalf);
            ldsm4(wl[ks], w_lo + (wm * 16 + arow) * WSS + ks * 16 + ahalf);
        }
        __syncthreads();
        if (t + 1 < ntiles) {
            stage_kv128(Vhi, Vlo, kv_hi, kv_lo, b, h, kt + 128, tid);
            CP_COMMIT;
        }

#pragma unroll
        for (int ks = 0; ks < 8; ks++) {
            float (*acc)[4] = (ks & 1) ? accb : acca;
#pragma unroll
            for (int n8 = 0; n8 < 2; n8++)
                mma_bf16(acc[n8], wh[ks], vh[ks][n8 * 2], vh[ks][n8 * 2 + 1]);
        }
#pragma unroll
        for (int ks = 0; ks < 8; ks++) {
            float (*acc)[4] = (ks & 1) ? accb : acca;
#pragma unroll
            for (int n8 = 0; n8 < 2; n8++)
                mma_bf16(acc[n8], wh[ks], vl[ks][n8 * 2], vl[ks][n8 * 2 + 1]);
        }
#pragma unroll
        for (int ks = 0; ks < 8; ks++) {
            float (*acc)[4] = (ks & 1) ? accb : acca;
#pragma unroll
            for (int n8 = 0; n8 < 2; n8++)
                mma_bf16(acc[n8], wl[ks], vh[ks][n8 * 2], vh[ks][n8 * 2 + 1]);
        }
        __syncthreads();
    }

#pragma unroll
    for (int n8 = 0; n8 < 2; n8++) {
        int r0 = wm * 16 + (lane >> 2);
        int dc = wn * 16 + n8 * 8 + (lane & 3) * 2;
        float zi0 = zinv[r0];
        float zi8 = zinv[r0 + 8];
        float2 s0 = *(const float2*)&Suf[((size_t)bh * SEQ + q0 + r0) * HD + dc];
        float2 s8 = *(const float2*)&Suf[((size_t)bh * SEQ + q0 + r0 + 8) * HD + dc];
        float v00 = (acca[n8][0] + accb[n8][0] + s0.x) * zi0;
        float v01 = (acca[n8][1] + accb[n8][1] + s0.y) * zi0;
        float v10 = (acca[n8][2] + accb[n8][2] + s8.x) * zi8;
        float v11 = (acca[n8][3] + accb[n8][3] + s8.y) * zi8;
        __nv_bfloat162 h0, l0, h1, l1;
        h0.x = __float2bfloat16(v00); h0.y = __float2bfloat16(v01);
        l0.x = __float2bfloat16(v00 - __bfloat162float(h0.x));
        l0.y = __float2bfloat16(v01 - __bfloat162float(h0.y));
        h1.x = __float2bfloat16(v10); h1.y = __float2bfloat16(v11);
        l1.x = __float2bfloat16(v10 - __bfloat162float(h1.x));
        l1.y = __float2bfloat16(v11 - __bfloat162float(h1.y));
        size_t o0 = ((size_t)(b * SEQ + q0 + r0)) * EMB + h * HD + dc;
        size_t o8 = ((size_t)(b * SEQ + q0 + r0 + 8)) * EMB + h * HD + dc;
        *(__nv_bfloat162*)&Chi[o0] = h0;
        *(__nv_bfloat162*)&Clo[o0] = l0;
        *(__nv_bfloat162*)&Chi[o8] = h1;
        *(__nv_bfloat162*)&Clo[o8] = l1;
    }
}

// ---------------- launch ----------------------------------------------------
extern "C" void kernel_launch(void* const* d_in, const int* in_sizes, int n_in,
                              void* d_out, int out_size)
{
    const float* query = (const float*)d_in[0];
    const float* key   = (const float*)d_in[1];
    const float* value = (const float*)d_in[2];
    const float* cons  = (const float*)d_in[3];
    const float* Wq = (const float*)d_in[5];
    const float* bq = (const float*)d_in[6];
    const float* Wk = (const float*)d_in[7];
    const float* bk = (const float*)d_in[8];
    const float* Wv = (const float*)d_in[9];
    const float* bv = (const float*)d_in[10];
    const float* Wo = (const float*)d_in[11];
    const float* bo = (const float*)d_in[12];
    const float* Wc = (const float*)d_in[13];
    const float* bc = (const float*)d_in[14];

    float* qp; cudaGetSymbolAddress((void**)&qp, g_q);
    float* kp; cudaGetSymbolAddress((void**)&kp, g_k);
    float* vp; cudaGetSymbolAddress((void**)&vp, g_v);
    float* cp; cudaGetSymbolAddress((void**)&cp, g_ctx);
    float* cwp; cudaGetSymbolAddress((void**)&cwp, g_cw);
    float* sufp; cudaGetSymbolAddress((void**)&sufp, g_vsuf);
    __nv_bfloat16* ahi; cudaGetSymbolAddress((void**)&ahi, g_ahi);
    __nv_bfloat16* alo; cudaGetSymbolAddress((void**)&alo, g_alo);
    __nv_bfloat16* whi; cudaGetSymbolAddress((void**)&whi, g_whi);
    __nv_bfloat16* wlo; cudaGetSymbolAddress((void**)&wlo, g_wlo);

    const int M = BATCH * SEQ;
    const int A4 = M * EMB / 4;
    const int W4 = EMB * EMB / 4;
    const size_t AE = (size_t)M * EMB;
    const size_t WE = (size_t)EMB * EMB;

    __nv_bfloat16* qhi = (__nv_bfloat16*)qp;  __nv_bfloat16* qlo = qhi + AE;
    __nv_bfloat16* khi = (__nv_bfloat16*)kp;  __nv_bfloat16* klo = khi + AE;
    __nv_bfloat16* vhi = (__nv_bfloat16*)vp;  __nv_bfloat16* vlo = vhi + AE;
    __nv_bfloat16* chi = (__nv_bfloat16*)cp;  __nv_bfloat16* clo = chi + AE;

    float* out = (float*)d_out;
    float* attn_out = out + (size_t)BATCH * SEQ * EMB;

    cudaFuncSetAttribute(gemm_qkv, cudaFuncAttributeMaxDynamicSharedMemorySize, GEMM_SMEM);
    cudaFuncSetAttribute(gemm_single, cudaFuncAttributeMaxDynamicSharedMemorySize, GEMM_SMEM);
    cudaFuncSetAttribute(attn_mma_kernel, cudaFuncAttributeMaxDynamicSharedMemorySize, ATTN_SMEM);

    dim3 sa_grid((A4 + 255) / 256, 3);
    split_act3_kernel<<<sa_grid, 256>>>(query, key, value, ahi, alo, A4);
    dim3 sw_grid((W4 + 255) / 256, 4);
    split_w4_kernel<<<sw_grid, 256>>>(Wq, Wk, Wv, Wo, whi, wlo, W4);

    dim3 qkv_grid(EMB / BN, M / BM, 3);
    gemm_qkv<<<qkv_grid, 128, GEMM_SMEM>>>(
        ahi, alo, whi, wlo, bq, bk, bv,
        qhi, qlo, khi, klo, vhi, vlo);

    cw_kernel<<<M / 8, 256>>>(query, Wc, bc, cwp);
    vsuffix_hl_kernel<<<BATCH * NH, 256>>>(vhi, vlo, sufp);

    dim3 attn_grid(SEQ / AR, BATCH * NH);
    attn_mma_kernel<<<attn_grid, 256, ATTN_SMEM>>>(
        qhi, qlo, khi, klo, vhi, vlo, cwp, cons, sufp, attn_out, chi, clo);

    dim3 gemm_grid(EMB / BN, M / BM);
    gemm_single<<<gemm_grid, 128, GEMM_SMEM>>>(
        chi, clo, whi + 3 * WE, wlo + 3 * WE, bo, out);
}

// round 17
// speedup vs baseline: 1.0571x; 1.0285x over previous
#include <cuda_runtime.h>
#include <cuda_bf16.h>
#include <math.h>
#include <stdint.h>

#define EMB 1024
#define SEQ 1024
#define BATCH 4
#define NH 16
#define HD 64

// ---------------- scratch (device globals; no allocation allowed) ----------
__device__ float g_q[BATCH * SEQ * EMB];
__device__ float g_k[BATCH * SEQ * EMB];
__device__ float g_v[BATCH * SEQ * EMB];
__device__ float g_ctx[BATCH * SEQ * EMB];
__device__ float g_cw[BATCH * SEQ * NH];
__device__ float g_vsuf[BATCH * NH * SEQ * HD];
__device__ __nv_bfloat16 g_ahi[3][BATCH * SEQ * EMB];
__device__ __nv_bfloat16 g_alo[3][BATCH * SEQ * EMB];
__device__ __nv_bfloat16 g_whi[4][EMB * EMB];
__device__ __nv_bfloat16 g_wlo[4][EMB * EMB];

// ---------------- fast exp: FFMA-only ---------------------------------------
__device__ __forceinline__ float fast_exp(float x)
{
    x = fmaxf(x, -80.0f);
    const float L2E = 1.4426950408889634f;
    float t = fmaf(x, L2E, 12582912.0f);
    float i = t - 12582912.0f;
    float f = fmaf(x, L2E, -i);
    float p = 1.3333558146e-3f;
    p = fmaf(p, f, 9.6181291918e-3f);
    p = fmaf(p, f, 5.5504108664e-2f);
    p = fmaf(p, f, 2.4022650696e-1f);
    p = fmaf(p, f, 6.9314718056e-1f);
    p = fmaf(p, f, 1.0f);
    return __int_as_float(__float_as_int(p) + ((int)i << 23));
}

// ---------------- mma / ldmatrix helpers -------------------------------------
__device__ __forceinline__ void ldsm4(uint32_t* r, const void* p)
{
    uint32_t a = (uint32_t)__cvta_generic_to_shared(p);
    asm volatile("ldmatrix.sync.aligned.m8n8.x4.shared.b16 {%0,%1,%2,%3},[%4];"
                 : "=r"(r[0]), "=r"(r[1]), "=r"(r[2]), "=r"(r[3]) : "r"(a));
}
__device__ __forceinline__ void ldsm4t(uint32_t* r, const void* p)
{
    uint32_t a = (uint32_t)__cvta_generic_to_shared(p);
    asm volatile("ldmatrix.sync.aligned.m8n8.x4.trans.shared.b16 {%0,%1,%2,%3},[%4];"
                 : "=r"(r[0]), "=r"(r[1]), "=r"(r[2]), "=r"(r[3]) : "r"(a));
}
__device__ __forceinline__ void mma_bf16(float* c, const uint32_t* a,
                                         uint32_t b0, uint32_t b1)
{
    asm("mma.sync.aligned.m16n8k16.row.col.f32.bf16.bf16.f32 "
        "{%0,%1,%2,%3},{%4,%5,%6,%7},{%8,%9},{%0,%1,%2,%3};"
        : "+f"(c[0]), "+f"(c[1]), "+f"(c[2]), "+f"(c[3])
        : "r"(a[0]), "r"(a[1]), "r"(a[2]), "r"(a[3]), "r"(b0), "r"(b1));
}

// ---------------- fp32 -> bf16 hi/lo split ----------------------------------
__device__ __forceinline__ void split4(
    const float* __restrict__ X, __nv_bfloat16* __restrict__ Hi,
    __nv_bfloat16* __restrict__ Lo, int i)
{
    float4 x = ((const float4*)X)[i];
    __nv_bfloat16 h0 = __float2bfloat16(x.x);
    __nv_bfloat16 h1 = __float2bfloat16(x.y);
    __nv_bfloat16 h2 = __float2bfloat16(x.z);
    __nv_bfloat16 h3 = __float2bfloat16(x.w);
    __nv_bfloat162 H0; H0.x = h0; H0.y = h1;
    __nv_bfloat162 H1; H1.x = h2; H1.y = h3;
    __nv_bfloat162 L0;
    L0.x = __float2bfloat16(x.x - __bfloat162float(h0));
    L0.y = __float2bfloat16(x.y - __bfloat162float(h1));
    __nv_bfloat162 L1;
    L1.x = __float2bfloat16(x.z - __bfloat162float(h2));
    L1.y = __float2bfloat16(x.w - __bfloat162float(h3));
    ((__nv_bfloat162*)Hi)[2 * i] = H0;
    ((__nv_bfloat162*)Hi)[2 * i + 1] = H1;
    ((__nv_bfloat162*)Lo)[2 * i] = L0;
    ((__nv_bfloat162*)Lo)[2 * i + 1] = L1;
}

__global__ __launch_bounds__(256) void split_act3_kernel(
    const float* __restrict__ X0, const float* __restrict__ X1,
    const float* __restrict__ X2, __nv_bfloat16* __restrict__ Hi,
    __nv_bfloat16* __restrict__ Lo, int n4)
{
    int i = blockIdx.x * 256 + threadIdx.x;
    if (i >= n4) return;
    int s = blockIdx.y;
    const float* X = (s == 0) ? X0 : (s == 1) ? X1 : X2;
    split4(X, Hi + (size_t)s * BATCH * SEQ * EMB,
           Lo + (size_t)s * BATCH * SEQ * EMB, i);
}

__global__ __launch_bounds__(256) void split_w4_kernel(
    const float* __restrict__ W0, const float* __restrict__ W1,
    const float* __restrict__ W2, const float* __restrict__ W3,
    __nv_bfloat16* __restrict__ Hi, __nv_bfloat16* __restrict__ Lo, int n4)
{
    int i = blockIdx.x * 256 + threadIdx.x;
    if (i >= n4) return;
    int s = blockIdx.y;
    const float* W = (s == 0) ? W0 : (s == 1) ? W1 : (s == 2) ? W2 : W3;
    split4(W, Hi + (size_t)s * EMB * EMB, Lo + (size_t)s * EMB * EMB, i);
}

// ---------------- fused bf16x3 GEMM: 4 warps, warp tile 64x64 ----------------
#define BM 128
#define BN 128
#define BK 32
#define ASTR 40
#define BSTR 136
#define A_ELEM (BM * ASTR)
#define B_ELEM (BK * BSTR)
#define STAGE_ELEM (2 * A_ELEM + 2 * B_ELEM)
#define GEMM_SMEM (2 * STAGE_ELEM * (int)sizeof(__nv_bfloat16))

#define CP_ASYNC16(dst, src) \
    asm volatile("cp.async.cg.shared.global [%0], [%1], 16;\n" :: "r"(dst), "l"(src))
#define CP_COMMIT asm volatile("cp.async.commit_group;\n" ::)
#define CP_WAITG(n) asm volatile("cp.async.wait_group %0;\n" :: "n"(n))

__device__ __forceinline__ void gemm_core(
    const __nv_bfloat16* __restrict__ Ahi, const __nv_bfloat16* __restrict__ Alo,
    const __nv_bfloat16* __restrict__ Bhi, const __nv_bfloat16* __restrict__ Blo,
    const float* __restrict__ bias, float* __restrict__ C,
    __nv_bfloat16* __restrict__ Chi, __nv_bfloat16* __restrict__ Clo,
    int M, int N, int K)
{
    extern __shared__ __align__(16) __nv_bfloat16 smem[];

    const int tid = threadIdx.x;
    const int lane = tid & 31;
    const int wid = tid >> 5;
    const int wm = wid & 1;
    const int wn = wid >> 1;
    const int row0 = blockIdx.y * BM;
    const int col0 = blockIdx.x * BN;

    float acc[4][8][4];
#pragma unroll
    for (int i = 0; i < 4; i++)
#pragma unroll
        for (int j = 0; j < 8; j++)
#pragma unroll
            for (int r = 0; r < 4; r++) acc[i][j][r] = 0.f;

    const int TOT = K / BK;

#define LOAD_STAGE(IT, BUF) do {                                               \
    int k0_ = (IT) * BK;                                                       \
    __nv_bfloat16* sa_hi = smem + (BUF) * STAGE_ELEM;                          \
    __nv_bfloat16* sa_lo = sa_hi + A_ELEM;                                     \
    __nv_bfloat16* sb_hi = sa_lo + A_ELEM;                                     \
    __nv_bfloat16* sb_lo = sb_hi + B_ELEM;                                     \
    _Pragma("unroll")                                                          \
    for (int li = 0; li < 4; li++) {                                           \
        int idx = tid + li * 128;                                              \
        int ar = idx >> 2, ac = (idx & 3) * 8;                                 \
        int br = idx >> 4, bc = (idx & 15) * 8;                                \
        CP_ASYNC16((uint32_t)__cvta_generic_to_shared(&sa_hi[ar * ASTR + ac]), \
                   Ahi + (size_t)(row0 + ar) * K + k0_ + ac);                  \
        CP_ASYNC16((uint32_t)__cvta_generic_to_shared(&sa_lo[ar * ASTR + ac]), \
                   Alo + (size_t)(row0 + ar) * K + k0_ + ac);                  \
        CP_ASYNC16((uint32_t)__cvta_generic_to_shared(&sb_hi[br * BSTR + bc]), \
                   Bhi + (size_t)(k0_ + br) * N + col0 + bc);                  \
        CP_ASYNC16((uint32_t)__cvta_generic_to_shared(&sb_lo[br * BSTR + bc]), \
                   Blo + (size_t)(k0_ + br) * N + col0 + bc);                  \
    }                                                                          \
} while (0)

    LOAD_STAGE(0, 0); CP_COMMIT;

    for (int it = 0; it < TOT; it++) {
        const int buf = it & 1;
        if (it + 1 < TOT) {
            LOAD_STAGE(it + 1, (it + 1) & 1);
            CP_COMMIT;
            CP_WAITG(1);
        } else {
            CP_WAITG(0);
        }
        __syncthreads();

        const __nv_bfloat16* sa_hi = smem + buf * STAGE_ELEM;
        const __nv_bfloat16* sa_lo = sa_hi + A_ELEM;
        const __nv_bfloat16* sb_hi = sa_lo + A_ELEM;
        const __nv_bfloat16* sb_lo = sb_hi + B_ELEM;

#pragma unroll
        for (int ks = 0; ks < 2; ks++) {
            uint32_t ahi[4][4], alo[4][4], bhi[4][4], blo[4][4];
#pragma unroll
            for (int mi = 0; mi < 4; mi++) {
                int roff = (wm * 64 + mi * 16 + (lane & 15)) * ASTR +
                           ks * 16 + (lane >> 4) * 8;
                ldsm4(ahi[mi], &sa_hi[roff]);
                ldsm4(alo[mi], &sa_lo[roff]);
            }
#pragma unroll
            for (int bi = 0; bi < 4; bi++) {
                int boff = (ks * 16 + (lane & 15)) * BSTR +
                           wn * 64 + bi * 16 + (lane >> 4) * 8;
                ldsm4t(bhi[bi], &sb_hi[boff]);
                ldsm4t(blo[bi], &sb_lo[boff]);
            }
#pragma unroll
            for (int bi = 0; bi < 4; bi++)
#pragma unroll
                for (int p = 0; p < 2; p++)
#pragma unroll
                    for (int mi = 0; mi < 4; mi++)
                        mma_bf16(acc[mi][bi * 2 + p], ahi[mi],
                                 bhi[bi][p * 2], bhi[bi][p * 2 + 1]);
#pragma unroll
            for (int bi = 0; bi < 4; bi++)
#pragma unroll
                for (int p = 0; p < 2; p++)
#pragma unroll
                    for (int mi = 0; mi < 4; mi++)
                        mma_bf16(acc[mi][bi * 2 + p], ahi[mi],
                                 blo[bi][p * 2], blo[bi][p * 2 + 1]);
#pragma unroll
            for (int bi = 0; bi < 4; bi++)
#pragma unroll
                for (int p = 0; p < 2; p++)
#pragma unroll
                    for (int mi = 0; mi < 4; mi++)
                        mma_bf16(acc[mi][bi * 2 + p], alo[mi],
                                 bhi[bi][p * 2], bhi[bi][p * 2 + 1]);
        }
        __syncthreads();
    }

    const int g = lane >> 2;
    const int t = lane & 3;
#pragma unroll
    for (int ni = 0; ni < 8; ni++) {
        int col = col0 + wn * 64 + ni * 8 + t * 2;
        float b0 = bias[col], b1 = bias[col + 1];
#pragma unroll
        for (int mi = 0; mi < 4; mi++) {
            int row = row0 + wm * 64 + mi * 16 + g;
            float v00 = acc[mi][ni][0] + b0, v01 = acc[mi][ni][1] + b1;
            float v10 = acc[mi][ni][2] + b0, v11 = acc[mi][ni][3] + b1;
            if (Chi) {
                __nv_bfloat162 h0, l0, h1, l1;
                h0.x = __float2bfloat16(v00);
                h0.y = __float2bfloat16(v01);
                l0.x = __float2bfloat16(v00 - __bfloat162float(h0.x));
                l0.y = __float2bfloat16(v01 - __bfloat162float(h0.y));
                h1.x = __float2bfloat16(v10);
                h1.y = __float2bfloat16(v11);
                l1.x = __float2bfloat16(v10 - __bfloat162float(h1.x));
                l1.y = __float2bfloat16(v11 - __bfloat162float(h1.y));
                *(__nv_bfloat162*)&Chi[(size_t)row * N + col] = h0;
                *(__nv_bfloat162*)&Clo[(size_t)row * N + col] = l0;
                *(__nv_bfloat162*)&Chi[(size_t)(row + 8) * N + col] = h1;
                *(__nv_bfloat162*)&Clo[(size_t)(row + 8) * N + col] = l1;
            } else {
                float2 o0 = { v00, v01 };
                float2 o1 = { v10, v11 };
                *(float2*)&C[(size_t)row * N + col] = o0;
                *(float2*)&C[(size_t)(row + 8) * N + col] = o1;
            }
        }
    }
#undef LOAD_STAGE
}

// cw path run by extra grid.z slices of the QKV launch (128 threads, 8 rows)
__device__ __forceinline__ void cw_block(
    const float* __restrict__ query, const float* __restrict__ Wc,
    const float* __restrict__ bc, float* __restrict__ CW, int row0)
{
    extern __shared__ __align__(16) float qs[];   // 8 * 1024 floats
    const int tid = threadIdx.x;

    for (int idx = tid; idx < 2048; idx += 128) {
        int r = idx >> 8;
        int c4 = (idx & 255) * 4;
        *(float4*)&qs[r * 1024 + c4] = *(const float4*)&query[(size_t)(row0 + r) * EMB + c4];
    }
    __syncthreads();

    const int lane = tid & 31;
    const int wrp = tid >> 5;        // 0..3
    const int h = lane & 15;
    const int ks = lane >> 4;

#pragma unroll
    for (int rr = 0; rr < 2; rr++) {
        const int r = wrp * 2 + rr;
        const float* q = &qs[r * 1024 + ks * 512];
        const float* wc = &Wc[(size_t)(ks * 512) * NH + h];

        float a0 = 0.f, a1 = 0.f, a2 = 0.f, a3 = 0.f;
#pragma unroll 4
        for (int i = 0; i < 512; i += 4) {
            float4 qv = *(const float4*)&q[i];
            a0 += qv.x * wc[(i + 0) * NH];
            a1 += qv.y * wc[(i + 1) * NH];
            a2 += qv.z * wc[(i + 2) * NH];
            a3 += qv.w * wc[(i + 3) * NH];
        }
        float acc = (a0 + a1) + (a2 + a3);
        acc += __shfl_xor_sync(0xffffffffu, acc, 16);
        acc += bc[h];

        float m = acc;
#pragma unroll
        for (int o = 8; o > 0; o >>= 1) m = fmaxf(m, __shfl_xor_sync(0xffffffffu, m, o, 16));
        float e = fast_exp(acc - m);
        float s = e;
#pragma unroll
        for (int o = 8; o > 0; o >>= 1) s += __shfl_xor_sync(0xffffffffu, s, o, 16);
        if (ks == 0) CW[(size_t)(row0 + r) * NH + h] = e / s;
    }
}

__global__ __launch_bounds__(128, 2) void gemm_qkv_cw(
    const __nv_bfloat16* __restrict__ Ahi, const __nv_bfloat16* __restrict__ Alo,
    const __nv_bfloat16* __restrict__ Whi, const __nv_bfloat16* __restrict__ Wlo,
    const float* __restrict__ b0, const float* __restrict__ b1,
    const float* __restrict__ b2,
    __nv_bfloat16* __restrict__ o0h, __nv_bfloat16* __restrict__ o0l,
    __nv_bfloat16* __restrict__ o1h, __nv_bfloat16* __restrict__ o1l,
    __nv_bfloat16* __restrict__ o2h, __nv_bfloat16* __restrict__ o2l,
    const float* __restrict__ query, const float* __restrict__ Wc,
    const float* __restrict__ bc, float* __restrict__ CW)
{
    const int s = blockIdx.z;
    if (s < 3) {
        const size_t AE = (size_t)BATCH * SEQ * EMB;
        const size_t WE = (size_t)EMB * EMB;
        const float* bias = (s == 0) ? b0 : (s == 1) ? b1 : b2;
        __nv_bfloat16* ch = (s == 0) ? o0h : (s == 1) ? o1h : o2h;
        __nv_bfloat16* cl = (s == 0) ? o0l : (s == 1) ? o1l : o2l;
        gemm_core(Ahi + s * AE, Alo + s * AE, Whi + s * WE, Wlo + s * WE,
                  bias, nullptr, ch, cl, BATCH * SEQ, EMB, EMB);
    } else {
        int cb = (s - 3) * 256 + blockIdx.y * 8 + blockIdx.x;  // 0..511
        cw_block(query, Wc, bc, CW, cb * 8);
    }
}

__global__ __launch_bounds__(128, 2) void gemm_single(
    const __nv_bfloat16* __restrict__ Ahi, const __nv_bfloat16* __restrict__ Alo,
    const __nv_bfloat16* __restrict__ Whi, const __nv_bfloat16* __restrict__ Wlo,
    const float* __restrict__ bias, float* __restrict__ C)
{
    gemm_core(Ahi, Alo, Whi, Wlo, bias, C, nullptr, nullptr,
              BATCH * SEQ, EMB, EMB);
}

// ---------------- suffix sums of V (bf16 hi/lo) -------------------------------
__global__ __launch_bounds__(256) void vsuffix_hl_kernel(
    const __nv_bfloat16* __restrict__ Vhi, const __nv_bfloat16* __restrict__ Vlo,
    float* __restrict__ Suf)
{
    __shared__ float T[4][64];
    const int bh = blockIdx.x;
    const int b = bh >> 4;
    const int h = bh & 15;
    const int t = threadIdx.x;
    const int p = t >> 6;
    const int d = t & 63;

    const size_t base = (size_t)b * SEQ * EMB + h * HD + d;
    float* sufb = Suf + (size_t)bh * SEQ * HD + d;

    const int k0 = p * 256;
    float s = 0.f;
#pragma unroll 4
    for (int k = k0; k < k0 + 256; k++) {
        size_t o = base + (size_t)k * EMB;
        s += __bfloat162float(Vhi[o]) + __bfloat162float(Vlo[o]);
    }
    T[p][d] = s;
    __syncthreads();

    float acc = 0.f;
    for (int pp = p + 1; pp < 4; pp++) acc += T[pp][d];
    for (int k = k0 + 252; k >= k0; k -= 4) {
        size_t o3 = base + (size_t)(k + 3) * EMB;
        size_t o2 = base + (size_t)(k + 2) * EMB;
        size_t o1 = base + (size_t)(k + 1) * EMB;
        size_t o0 = base + (size_t)(k + 0) * EMB;
        float v3 = __bfloat162float(Vhi[o3]) + __bfloat162float(Vlo[o3]);
        float v2 = __bfloat162float(Vhi[o2]) + __bfloat162float(Vlo[o2]);
        float v1 = __bfloat162float(Vhi[o1]) + __bfloat162float(Vlo[o1]);
        float v0 = __bfloat162float(Vhi[o0]) + __bfloat162float(Vlo[o0]);
        sufb[(size_t)(k + 3) * HD] = acc; acc += v3;
        sufb[(size_t)(k + 2) * HD] = acc; acc += v2;
        sufb[(size_t)(k + 1) * HD] = acc; acc += v1;
        sufb[(size_t)(k + 0) * HD] = acc; acc += v0;
    }
}

// ---------------- tensor-core attention --------------------------------------
#define AR 32
#define QSS 72
#define WSS 136
#define EST 1036
#define ESC_BYTES (AR * EST * 4)
#define KV_OFF    ESC_BYTES
#define KV_BYTES  (128 * QSS * 2)
#define QH_OFF    (KV_OFF + 2 * KV_BYTES)
#define QMAT_BYTES (AR * QSS * 2)
#define WH_OFF    (QH_OFF + 2 * QMAT_BYTES)
#define WMAT_BYTES (AR * WSS * 2)
#define ATTN_SMEM (WH_OFF + 2 * WMAT_BYTES)

__device__ __forceinline__ void stage_kv128(
    const __nv_bfloat16* __restrict__ Ghi, const __nv_bfloat16* __restrict__ Glo,
    __nv_bfloat16* s_hi, __nv_bfloat16* s_lo, int b, int h, int kt, int tid)
{
#pragma unroll
    for (int li = 0; li < 4; li++) {
        int c = tid + li * 256;
        int r = c >> 3, c16 = c & 7;
        size_t goff = (size_t)(b * SEQ + kt + r) * EMB + h * HD + c16 * 8;
        CP_ASYNC16((uint32_t)__cvta_generic_to_shared(s_hi + r * QSS + c16 * 8), Ghi + goff);
        CP_ASYNC16((uint32_t)__cvta_generic_to_shared(s_lo + r * QSS + c16 * 8), Glo + goff);
    }
}

__global__ __launch_bounds__(256, 1) void attn_mma_kernel(
    const __nv_bfloat16* __restrict__ Qhi, const __nv_bfloat16* __restrict__ Qlo,
    const __nv_bfloat16* __restrict__ Khi, const __nv_bfloat16* __restrict__ Klo,
    const __nv_bfloat16* __restrict__ Vhi, const __nv_bfloat16* __restrict__ Vlo,
    const float* __restrict__ CW, const float* __restrict__ cons,
    const float* __restrict__ Suf, float* __restrict__ attn_out,
    __nv_bfloat16* __restrict__ Chi, __nv_bfloat16* __restrict__ Clo)
{
    extern __shared__ __align__(16) char smraw[];
    float* esc = (float*)smraw;
    __nv_bfloat16* kv_hi = (__nv_bfloat16*)(smraw + KV_OFF);
    __nv_bfloat16* kv_lo = (__nv_bfloat16*)(smraw + KV_OFF + KV_BYTES);
    __nv_bfloat16* q_hi  = (__nv_bfloat16*)(smraw + QH_OFF);
    __nv_bfloat16* q_lo  = (__nv_bfloat16*)(smraw + QH_OFF + QMAT_BYTES);
    __nv_bfloat16* w_hi  = (__nv_bfloat16*)(smraw + WH_OFF);
    __nv_bfloat16* w_lo  = (__nv_bfloat16*)(smraw + WH_OFF + WMAT_BYTES);
    __shared__ float zinv[AR];

    const int tid = threadIdx.x;
    const int lane = tid & 31;
    const int w = tid >> 5;
    const int bh = blockIdx.y;
    const int b = bh >> 4;
    const int h = bh & 15;
    const int q0 = (gridDim.x - 1 - blockIdx.x) * AR;
    const int kmax = q0 + AR;
    const int ntiles = (kmax + 127) >> 7;
    const float INV_SCALE = 1.0f / (8.0f * sqrtf(1.61803398874989485f));

#pragma unroll
    for (int li = 0; li < 2; li++) {
        int c = tid + li * 256;
        int r = (c & 255) >> 3;
        int c16 = c & 7;
        const __nv_bfloat16* src = ((c < 256) ? Qhi : Qlo)
            + (size_t)(b * SEQ + q0 + r) * EMB + h * HD + c16 * 8;
        __nv_bfloat16* dst = ((c < 256) ? q_hi : q_lo) + r * QSS + c16 * 8;
        CP_ASYNC16((uint32_t)__cvta_generic_to_shared(dst), src);
    }
    CP_COMMIT;
    stage_kv128(Khi, Klo, kv_hi, kv_lo, b, h, 0, tid);
    CP_COMMIT;

    CP_WAITG(1);
    __syncthreads();
    uint32_t qh[4][2][4], ql[4][2][4];
#pragma unroll
    for (int ks = 0; ks < 4; ks++) {
        const int arow = lane & 15;
        const int acol = ks * 16 + (lane >> 4) * 8;
#pragma unroll
        for (int m = 0; m < 2; m++) {
            ldsm4(qh[ks][m], q_hi + (m * 16 + arow) * QSS + acol);
            ldsm4(ql[ks][m], q_lo + (m * 16 + arow) * QSS + acol);
        }
    }

    for (int t = 0; t < ntiles; t++) {
        const int kt = t * 128;
        // warp's 16-column k range fully masked? (first col > max q in block)
        const bool active = (kt + w * 16) <= (q0 + AR - 1);
        CP_WAITG(0);
        __syncthreads();

        uint32_t kh[4][4], kl[4][4];
        if (active) {
#pragma unroll
            for (int ks = 0; ks < 4; ks++) {
                const int arow = lane & 15;
                const int acol = ks * 16 + (lane >> 4) * 8;
                ldsm4(kh[ks], kv_hi + (w * 16 + arow) * QSS + acol);
                ldsm4(kl[ks], kv_lo + (w * 16 + arow) * QSS + acol);
            }
        }
        __syncthreads();
        if (t + 1 < ntiles) {
            stage_kv128(Khi, Klo, kv_hi, kv_lo, b, h, kt + 128, tid);
            CP_COMMIT;
        }

        if (active) {
            float accs[2][2][4];
#pragma unroll
            for (int m = 0; m < 2; m++)
#pragma unroll
                for (int n = 0; n < 2; n++)
#pragma unroll
                    for (int r = 0; r < 4; r++) accs[m][n][r] = 0.f;

#pragma unroll
            for (int ks = 0; ks < 4; ks++)
#pragma unroll
                for (int m = 0; m < 2; m++)
#pragma unroll
                    for (int n8 = 0; n8 < 2; n8++)
                        mma_bf16(accs[m][n8], qh[ks][m], kh[ks][n8], kh[ks][n8 + 2]);
#pragma unroll
            for (int ks = 0; ks < 4; ks++)
#pragma unroll
                for (int m = 0; m < 2; m++)
#pragma unroll
                    for (int n8 = 0; n8 < 2; n8++)
                        mma_bf16(accs[m][n8], qh[ks][m], kl[ks][n8], kl[ks][n8 + 2]);
#pragma unroll
            for (int ks = 0; ks < 4; ks++)
#pragma unroll
                for (int m = 0; m < 2; m++)
#pragma unroll
                    for (int n8 = 0; n8 < 2; n8++)
                        mma_bf16(accs[m][n8], ql[ks][m], kh[ks][n8], kh[ks][n8 + 2]);

#pragma unroll
            for (int m = 0; m < 2; m++)
#pragma unroll
                for (int n8 = 0; n8 < 2; n8++) {
                    int row = m * 16 + (lane >> 2);
                    int col = kt + w * 16 + n8 * 8 + (lane & 3) * 2;
                    float2 lo = { accs[m][n8][0] * INV_SCALE, accs[m][n8][1] * INV_SCALE };
                    float2 hi = { accs[m][n8][2] * INV_SCALE, accs[m][n8][3] * INV_SCALE };
                    *(float2*)&esc[row * EST + col] = lo;
                    *(float2*)&esc[(row + 8) * EST + col] = hi;
                }
        }
    }
    stage_kv128(Vhi, Vlo, kv_hi, kv_lo, b, h, 0, tid);
    CP_COMMIT;
    __syncthreads();

    // ---- softmax1 -> rescale -> softmax2 numerators + FUSED attn write ----
    {
        const size_t abase = ((size_t)bh * SEQ + q0) * SEQ;
#pragma unroll
        for (int rr = 0; rr < 4; rr++) {
            int r = w * 4 + rr;
            int q = q0 + r;
            int kc = q + 1;
            float* row = &esc[r * EST];

            float m = -1e30f;
            for (int k = lane; k < kc; k += 32) m = fmaxf(m, row[k]);
#pragma unroll
            for (int o = 16; o > 0; o >>= 1) m = fmaxf(m, __shfl_xor_sync(0xffffffffu, m, o));

            float s = 0.f;
            for (int k = lane; k < kc; k += 32) {
                float p = fast_exp(row[k] - m);
                row[k] = p;
                s += p;
            }
#pragma unroll
            for (int o = 16; o > 0; o >>= 1) s += __shfl_xor_sync(0xffffffffu, s, o);

            float cb = cons[b * SEQ + q];
            float cwv = CW[(size_t)(b * SEQ + q) * NH + h];
            float fs = (1.f + cb * cwv) / s;

            float z2 = 0.f;
            for (int k = lane; k < kc; k += 32) {
                float e = fast_exp(row[k] * fs);
                row[k] = e;
                z2 += e;
            }
#pragma unroll
            for (int o = 16; o > 0; o >>= 1) z2 += __shfl_xor_sync(0xffffffffu, z2, o);
            z2 += (float)(SEQ - kc);
            float zi = 1.f / z2;
            if (lane == 0) zinv[r] = zi;

            float* gout = &attn_out[abase + (size_t)r * SEQ];
            for (int c4 = lane * 4; c4 < SEQ; c4 += 128) {
                float4 v;
                if (c4 + 3 <= q) {
                    v = *(float4*)&row[c4];
                    v.x *= zi; v.y *= zi; v.z *= zi; v.w *= zi;
                } else if (c4 > q) {
                    v.x = zi; v.y = zi; v.z = zi; v.w = zi;
                } else {
                    float4 e = *(float4*)&row[c4];
                    v.x = (c4 + 0 <= q) ? e.x * zi : zi;
                    v.y = (c4 + 1 <= q) ? e.y * zi : zi;
                    v.z = (c4 + 2 <= q) ? e.z * zi : zi;
                    v.w = (c4 + 3 <= q) ? e.w * zi : zi;
                }
                __stcs((float4*)&gout[c4], v);
            }
        }
    }
    __syncthreads();

    // ---- ctx phase: causal mask folded into the w-tile conversion ----
    const int wm = w & 1;
    const int wn = w >> 1;
    float acca[2][4], accb[2][4];
#pragma unroll
    for (int n = 0; n < 2; n++)
#pragma unroll
        for (int r = 0; r < 4; r++) { acca[n][r] = 0.f; accb[n][r] = 0.f; }

    for (int t = 0; t < ntiles; t++) {
        const int kt = t * 128;
#pragma unroll
        for (int e = 0; e < 16; e++) {
            int elem = tid + e * 256;
            int row = elem >> 7, col = elem & 127;
            float v = (kt + col <= q0 + row) ? esc[row * EST + kt + col] : 0.f;
            __nv_bfloat16 hv = __float2bfloat16(v);
            w_hi[row * WSS + col] = hv;
            w_lo[row * WSS + col] = __float2bfloat16(v - __bfloat162float(hv));
        }
        CP_WAITG(0);
        __syncthreads();

        uint32_t vh[8][4], vl[8][4], wh[8][4], wl[8][4];
#pragma unroll
        for (int ks = 0; ks < 8; ks++) {
            const int arow = lane & 15;
            const int ahalf = (lane >> 4) * 8;
            ldsm4t(vh[ks], kv_hi + (ks * 16 + arow) * QSS + wn * 16 + ahalf);
            ldsm4t(vl[ks], kv_lo + (ks * 16 + arow) * QSS + wn * 16 + ahalf);
            ldsm4(wh[ks], w_hi + (wm * 16 + arow) * WSS + ks * 16 + ahalf);
            ldsm4(wl[ks], w_lo + (wm * 16 + arow) * WSS + ks * 16 + ahalf);
        }
        __syncthreads();
        if (t + 1 < ntiles) {
            stage_kv128(Vhi, Vlo, kv_hi, kv_lo, b, h, kt + 128, tid);
            CP_COMMIT;
        }

#pragma unroll
        for (int ks = 0; ks < 8; ks++) {
            float (*acc)[4] = (ks & 1) ? accb : acca;
#pragma unroll
            for (int n8 = 0; n8 < 2; n8++)
                mma_bf16(acc[n8], wh[ks], vh[ks][n8 * 2], vh[ks][n8 * 2 + 1]);
        }
#pragma unroll
        for (int ks = 0; ks < 8; ks++) {
            float (*acc)[4] = (ks & 1) ? accb : acca;
#pragma unroll
            for (int n8 = 0; n8 < 2; n8++)
                mma_bf16(acc[n8], wh[ks], vl[ks][n8 * 2], vl[ks][n8 * 2 + 1]);
        }
#pragma unroll
        for (int ks = 0; ks < 8; ks++) {
            float (*acc)[4] = (ks & 1) ? accb : acca;
#pragma unroll
            for (int n8 = 0; n8 < 2; n8++)
                mma_bf16(acc[n8], wl[ks], vh[ks][n8 * 2], vh[ks][n8 * 2 + 1]);
        }
        __syncthreads();
    }

#pragma unroll
    for (int n8 = 0; n8 < 2; n8++) {
        int r0 = wm * 16 + (lane >> 2);
        int dc = wn * 16 + n8 * 8 + (lane & 3) * 2;
        float zi0 = zinv[r0];
        float zi8 = zinv[r0 + 8];
        float2 s0 = *(const float2*)&Suf[((size_t)bh * SEQ + q0 + r0) * HD + dc];
        float2 s8 = *(const float2*)&Suf[((size_t)bh * SEQ + q0 + r0 + 8) * HD + dc];
        float v00 = (acca[n8][0] + accb[n8][0] + s0.x) * zi0;
        float v01 = (acca[n8][1] + accb[n8][1] + s0.y) * zi0;
        float v10 = (acca[n8][2] + accb[n8][2] + s8.x) * zi8;
        float v11 = (acca[n8][3] + accb[n8][3] + s8.y) * zi8;
        __nv_bfloat162 h0, l0, h1, l1;
        h0.x = __float2bfloat16(v00); h0.y = __float2bfloat16(v01);
        l0.x = __float2bfloat16(v00 - __bfloat162float(h0.x));
        l0.y = __float2bfloat16(v01 - __bfloat162float(h0.y));
        h1.x = __float2bfloat16(v10); h1.y = __float2bfloat16(v11);
        l1.x = __float2bfloat16(v10 - __bfloat162float(h1.x));
        l1.y = __float2bfloat16(v11 - __bfloat162float(h1.y));
        size_t o0 = ((size_t)(b * SEQ + q0 + r0)) * EMB + h * HD + dc;
        size_t o8 = ((size_t)(b * SEQ + q0 + r0 + 8)) * EMB + h * HD + dc;
        *(__nv_bfloat162*)&Chi[o0] = h0;
        *(__nv_bfloat162*)&Clo[o0] = l0;
        *(__nv_bfloat162*)&Chi[o8] = h1;
        *(__nv_bfloat162*)&Clo[o8] = l1;
    }
}

// ---------------- launch ----------------------------------------------------
extern "C" void kernel_launch(void* const* d_in, const int* in_sizes, int n_in,
                              void* d_out, int out_size)
{
    const float* query = (const float*)d_in[0];
    const float* key   = (const float*)d_in[1];
    const float* value = (const float*)d_in[2];
    const float* cons  = (const float*)d_in[3];
    const float* Wq = (const float*)d_in[5];
    const float* bq = (const float*)d_in[6];
    const float* Wk = (const float*)d_in[7];
    const float* bk = (const float*)d_in[8];
    const float* Wv = (const float*)d_in[9];
    const float* bv = (const float*)d_in[10];
    const float* Wo = (const float*)d_in[11];
    const float* bo = (const float*)d_in[12];
    const float* Wc = (const float*)d_in[13];
    const float* bc = (const float*)d_in[14];

    float* qp; cudaGetSymbolAddress((void**)&qp, g_q);
    float* kp; cudaGetSymbolAddress((void**)&kp, g_k);
    float* vp; cudaGetSymbolAddress((void**)&vp, g_v);
    float* cp; cudaGetSymbolAddress((void**)&cp, g_ctx);
    float* cwp; cudaGetSymbolAddress((void**)&cwp, g_cw);
    float* sufp; cudaGetSymbolAddress((void**)&sufp, g_vsuf);
    __nv_bfloat16* ahi; cudaGetSymbolAddress((void**)&ahi, g_ahi);
    __nv_bfloat16* alo; cudaGetSymbolAddress((void**)&alo, g_alo);
    __nv_bfloat16* whi; cudaGetSymbolAddress((void**)&whi, g_whi);
    __nv_bfloat16* wlo; cudaGetSymbolAddress((void**)&wlo, g_wlo);

    const int M = BATCH * SEQ;
    const int A4 = M * EMB / 4;
    const int W4 = EMB * EMB / 4;
    const size_t AE = (size_t)M * EMB;
    const size_t WE = (size_t)EMB * EMB;

    __nv_bfloat16* qhi = (__nv_bfloat16*)qp;  __nv_bfloat16* qlo = qhi + AE;
    __nv_bfloat16* khi = (__nv_bfloat16*)kp;  __nv_bfloat16* klo = khi + AE;
    __nv_bfloat16* vhi = (__nv_bfloat16*)vp;  __nv_bfloat16* vlo = vhi + AE;
    __nv_bfloat16* chi = (__nv_bfloat16*)cp;  __nv_bfloat16* clo = chi + AE;

    float* out = (float*)d_out;
    float* attn_out = out + (size_t)BATCH * SEQ * EMB;

    cudaFuncSetAttribute(gemm_qkv_cw, cudaFuncAttributeMaxDynamicSharedMemorySize, GEMM_SMEM);
    cudaFuncSetAttribute(gemm_single, cudaFuncAttributeMaxDynamicSharedMemorySize, GEMM_SMEM);
    cudaFuncSetAttribute(attn_mma_kernel, cudaFuncAttributeMaxDynamicSharedMemorySize, ATTN_SMEM);

    dim3 sa_grid((A4 + 255) / 256, 3);
    split_act3_kernel<<<sa_grid, 256>>>(query, key, value, ahi, alo, A4);
    dim3 sw_grid((W4 + 255) / 256, 4);
    split_w4_kernel<<<sw_grid, 256>>>(Wq, Wk, Wv, Wo, whi, wlo, W4);

    // fused QKV projections + cw softmax (z=0..2 gemm, z=3..4 cw)
    dim3 qkv_grid(EMB / BN, M / BM, 5);
    gemm_qkv_cw<<<qkv_grid, 128, GEMM_SMEM>>>(
        ahi, alo, whi, wlo, bq, bk, bv,
        qhi, qlo, khi, klo, vhi, vlo,
        query, Wc, bc, cwp);

    vsuffix_hl_kernel<<<BATCH * NH, 256>>>(vhi, vlo, sufp);

    dim3 attn_grid(SEQ / AR, BATCH * NH);
    attn_mma_kernel<<<attn_grid, 256, ATTN_SMEM>>>(
        qhi, qlo, khi, klo, vhi, vlo, cwp, cons, sufp, attn_out, chi, clo);

    dim3 gemm_grid(EMB / BN, M / BM);
    gemm_single<<<gemm_grid, 128, GEMM_SMEM>>>(
        chi, clo, whi + 3 * WE, wlo + 3 * WE, bo, out);
}